// round 12
// baseline (speedup 1.0000x reference)
#include <cuda_runtime.h>
#include <cuda_bf16.h>
#include <math.h>
#include <stdint.h>

// ---------------------------------------------------------------------------
// SwinTransformerBlock on GB300: warp-MMA bf16 GEMMs (128x256 tiles)
// + fused-window HMMA attention
// ---------------------------------------------------------------------------

#define M_TOK   100352
#define C_DIM   256
#define NHEADS  8
#define HDIM    32
#define NWIN    2048
#define NSEQ    49

__device__ __nv_bfloat16 g_zw [(size_t)M_TOK * C_DIM];
__device__ __nv_bfloat16 g_qkv[(size_t)M_TOK * 768];
__device__ __nv_bfloat16 g_o  [(size_t)M_TOK * C_DIM];
__device__ float         g_x2 [(size_t)M_TOK * C_DIM];
__device__ __nv_bfloat16 g_h  [(size_t)M_TOK * C_DIM];
__device__ __nv_bfloat16 g_fc1[(size_t)M_TOK * 1024];
__device__ __nv_bfloat16 g_wqkvT[768 * 256];
__device__ __nv_bfloat16 g_wprojT[256 * 256];
__device__ __nv_bfloat16 g_wfc1T[1024 * 256];
__device__ __nv_bfloat16 g_wfc2T[256 * 1024];
__device__ float g_battn[NHEADS * NSEQ * NSEQ];

// ---------------------------------------------------------------------------
__device__ __forceinline__ uint32_t smem_u32(const void* p) {
    uint32_t a;
    asm("{ .reg .u64 t; cvta.to.shared.u64 t, %1; cvt.u32.u64 %0, t; }" : "=r"(a) : "l"(p));
    return a;
}
__device__ __forceinline__ void ldsm4(uint32_t* r, uint32_t addr) {
    asm volatile("ldmatrix.sync.aligned.m8n8.x4.shared.b16 {%0,%1,%2,%3}, [%4];"
                 : "=r"(r[0]), "=r"(r[1]), "=r"(r[2]), "=r"(r[3]) : "r"(addr));
}
__device__ __forceinline__ void mma16816(float* c, const uint32_t* a, const uint32_t* b) {
    asm volatile(
        "mma.sync.aligned.m16n8k16.row.col.f32.bf16.bf16.f32 "
        "{%0,%1,%2,%3}, {%4,%5,%6,%7}, {%8,%9}, {%0,%1,%2,%3};"
        : "+f"(c[0]), "+f"(c[1]), "+f"(c[2]), "+f"(c[3])
        : "r"(a[0]), "r"(a[1]), "r"(a[2]), "r"(a[3]), "r"(b[0]), "r"(b[1]));
}
__device__ __forceinline__ uint32_t pack2(float a, float b) {
    __nv_bfloat162 h = __floats2bfloat162_rn(a, b);
    return *(uint32_t*)&h;
}
__device__ __forceinline__ float fexp(float x) {
    float z = fmaxf(x * 1.4426950408889634f, -126.0f);
    float t = z + 12582912.0f;
    int   i = __float_as_int(t) - 0x4B400000;
    float f = z - (t - 12582912.0f);
    float p = 0.00961804886f;
    p = fmaf(p, f, 0.05550410866f);
    p = fmaf(p, f, 0.24022650696f);
    p = fmaf(p, f, 0.69314718056f);
    p = fmaf(p, f, 1.0f);
    return __int_as_float(__float_as_int(p) + (i << 23));
}
#define CP16(dst, src) asm volatile("cp.async.cg.shared.global [%0], [%1], 16;" :: "r"(dst), "l"(src))
#define CP_COMMIT()    asm volatile("cp.async.commit_group;" ::: "memory")
#define CP_WAIT2()     asm volatile("cp.async.wait_group 2;" ::: "memory")

// ---------------------------------------------------------------------------
__global__ void wconv_kernel(const float* __restrict__ in, __nv_bfloat16* __restrict__ out,
                             int K, int N)
{
    int id = blockIdx.x * 256 + threadIdx.x;
    if (id >= K * N) return;
    int n = id / K, k = id - n * K;
    out[id] = __float2bfloat16(in[(size_t)k * N + n]);
}

__global__ void bias_kernel(const float* __restrict__ rel_table,
                            const int* __restrict__ rel_idx,
                            float* __restrict__ out)
{
    int idx = blockIdx.x * 256 + threadIdx.x;
    if (idx >= NHEADS * NSEQ * NSEQ) return;
    int h = idx / (NSEQ * NSEQ), nm = idx % (NSEQ * NSEQ);
    out[idx] = rel_table[rel_idx[nm] * NHEADS + h];
}

// ---------------------------------------------------------------------------
// LayerNorm: warp-per-token. 8 tokens / block.
// ---------------------------------------------------------------------------
__global__ __launch_bounds__(256) void ln_kernel(
    const float* __restrict__ x,
    const float* __restrict__ gamma,
    const float* __restrict__ beta,
    __nv_bfloat16* __restrict__ out,
    int shifted)
{
    int wid = threadIdx.x >> 5, lane = threadIdx.x & 31;
    int t = blockIdx.x * 8 + wid;
    int src;
    if (shifted) {
        int wi  = t / NSEQ;
        int pos = t - wi * NSEQ;
        int b    = wi >> 6;
        int wrem = wi & 63;
        int hs = (wrem >> 3) * 7 + pos / 7;
        int ws = (wrem & 7) * 7 + pos % 7;
        int sh = hs + 3; if (sh >= 56) sh -= 56;
        int sw = ws + 3; if (sw >= 56) sw -= 56;
        src = b * 3136 + sh * 56 + sw;
    } else {
        src = t;
    }
    const float* row = x + (size_t)src * C_DIM + lane * 8;
    float4 v0 = *(const float4*)(row);
    float4 v1 = *(const float4*)(row + 4);
    float v[8] = {v0.x, v0.y, v0.z, v0.w, v1.x, v1.y, v1.z, v1.w};
    float s = 0.f, s2 = 0.f;
    #pragma unroll
    for (int i = 0; i < 8; i++) { s += v[i]; s2 += v[i] * v[i]; }
    #pragma unroll
    for (int off = 16; off; off >>= 1) {
        s  += __shfl_xor_sync(0xffffffffu, s,  off);
        s2 += __shfl_xor_sync(0xffffffffu, s2, off);
    }
    float mean = s * (1.f / 256.f);
    float var  = s2 * (1.f / 256.f) - mean * mean;
    float r = rsqrtf(var + 1e-6f);
    const float* g4 = gamma + lane * 8;
    const float* b4 = beta + lane * 8;
    uint32_t o4[4];
    #pragma unroll
    for (int i = 0; i < 4; i++) {
        float a0 = (v[2*i]   - mean) * r * g4[2*i]   + b4[2*i];
        float a1 = (v[2*i+1] - mean) * r * g4[2*i+1] + b4[2*i+1];
        o4[i] = pack2(a0, a1);
    }
    *(uint4*)(out + (size_t)t * C_DIM + lane * 8) = *(uint4*)o4;
}

// ---------------------------------------------------------------------------
// Warp-MMA bf16 GEMM: tile 128x256, BK=32, 256 threads (8 warps, 2M x 4N),
// warp tile 64x64. 4-stage cp.async. Halves A-tile L2 re-reads vs BN=128.
// ---------------------------------------------------------------------------
#define KP 40
#define A_BYTES (128 * KP * 2)             // 10240
#define B_BYTES (256 * KP * 2)             // 20480
#define STAGE_B (A_BYTES + B_BYTES)        // 30720
#define B_OFF   A_BYTES

template<int EPI>
__global__ __launch_bounds__(256) void gemm_bf16(
    const __nv_bfloat16* __restrict__ A,
    const __nv_bfloat16* __restrict__ Bt,
    const float* __restrict__ bias,
    const float* __restrict__ residual,
    void* __restrict__ outv,
    int K, int Nc)
{
    extern __shared__ __align__(16) uint8_t smem[];
    __shared__ float sbias[256];

    const int tid = threadIdx.x;
    const int lane = tid & 31, wid = tid >> 5;
    const int wm = wid & 1;        // 2 warps in M (64 rows)
    const int wn = wid >> 1;       // 4 warps in N (64 cols)
    const int bn = blockIdx.x * 256, bm = blockIdx.y * 128;

    sbias[tid] = bias[bn + tid];

    const uint32_t sBase = smem_u32(smem);

    const int ldr = tid >> 2;            // 0..63
    const int ldc = (tid & 3) * 8;

    const uint32_t aRowB = (uint32_t)(wm * 64 + (lane & 15));
    const uint32_t aKH   = (lane & 16) ? 8u : 0u;
    const uint32_t bRowB = (uint32_t)(wn * 64 + (lane & 7) + ((lane & 16) ? 8 : 0));
    const uint32_t bKH   = (lane & 8) ? 8u : 0u;

    float acc[4][8][4];
    #pragma unroll
    for (int i = 0; i < 4; i++)
        #pragma unroll
        for (int j = 0; j < 8; j++)
            #pragma unroll
            for (int t = 0; t < 4; t++) acc[i][j][t] = 0.f;

    const int nk = K >> 5;

    #pragma unroll
    for (int s = 0; s < 3; s++) {
        uint32_t st = sBase + s * STAGE_B;
        const __nv_bfloat16* Ab = A + (size_t)bm * K + s * 32;
        const __nv_bfloat16* Bb = Bt + (size_t)bn * K + s * 32;
        #pragma unroll
        for (int j = 0; j < 2; j++) {      // A: 128 rows
            int r = ldr + j * 64;
            CP16(st + (uint32_t)(r * KP + ldc) * 2, Ab + (size_t)r * K + ldc);
        }
        #pragma unroll
        for (int j = 0; j < 4; j++) {      // B: 256 rows
            int r = ldr + j * 64;
            CP16(st + B_OFF + (uint32_t)(r * KP + ldc) * 2, Bb + (size_t)r * K + ldc);
        }
        CP_COMMIT();
    }

    for (int kc = 0; kc < nk; kc++) {
        CP_WAIT2();
        __syncthreads();

        if (kc + 3 < nk) {
            uint32_t st = sBase + ((kc + 3) & 3) * STAGE_B;
            const __nv_bfloat16* Ab = A + (size_t)bm * K + (kc + 3) * 32;
            const __nv_bfloat16* Bb = Bt + (size_t)bn * K + (kc + 3) * 32;
            #pragma unroll
            for (int j = 0; j < 2; j++) {
                int r = ldr + j * 64;
                CP16(st + (uint32_t)(r * KP + ldc) * 2, Ab + (size_t)r * K + ldc);
            }
            #pragma unroll
            for (int j = 0; j < 4; j++) {
                int r = ldr + j * 64;
                CP16(st + B_OFF + (uint32_t)(r * KP + ldc) * 2, Bb + (size_t)r * K + ldc);
            }
        }
        CP_COMMIT();

        const uint32_t aS = sBase + (kc & 3) * STAGE_B;
        const uint32_t bS = aS + B_OFF;
        #pragma unroll
        for (int ks = 0; ks < 2; ks++) {
            uint32_t af[4][4], bf[4][4];
            #pragma unroll
            for (int am = 0; am < 4; am++)
                ldsm4(af[am], aS + ((aRowB + am * 16) * KP + ks * 16 + aKH) * 2);
            #pragma unroll
            for (int g = 0; g < 4; g++)
                ldsm4(bf[g], bS + ((bRowB + g * 16) * KP + ks * 16 + bKH) * 2);
            #pragma unroll
            for (int am = 0; am < 4; am++)
                #pragma unroll
                for (int nn = 0; nn < 8; nn++)
                    mma16816(acc[am][nn], af[am], &bf[nn >> 1][(nn & 1) * 2]);
        }
    }

    const int n0 = bn + wn * 64 + (lane & 3) * 2;
    const int m0 = bm + wm * 64 + (lane >> 2);

    #pragma unroll
    for (int am = 0; am < 4; am++) {
        int mA = m0 + am * 16;
        int dstA = mA, dstB = mA + 8;
        if (EPI == 3) {
            #pragma unroll
            for (int h = 0; h < 2; h++) {
                int m = mA + h * 8;
                int wi  = m / NSEQ;
                int pos = m - wi * NSEQ;
                int b    = wi >> 6;
                int wrem = wi & 63;
                int hs = (wrem >> 3) * 7 + pos / 7;
                int ws = (wrem & 7) * 7 + pos % 7;
                int dh = hs + 3; if (dh >= 56) dh -= 56;
                int dw = ws + 3; if (dw >= 56) dw -= 56;
                int d = b * 3136 + dh * 56 + dw;
                if (h == 0) dstA = d; else dstB = d;
            }
        }
        #pragma unroll
        for (int nn = 0; nn < 8; nn++) {
            int col = n0 + nn * 8;
            float b0 = sbias[col - bn], b1 = sbias[col - bn + 1];
            float c0 = acc[am][nn][0] + b0, c1 = acc[am][nn][1] + b1;
            float c2 = acc[am][nn][2] + b0, c3 = acc[am][nn][3] + b1;
            if (EPI == 1) {
                c0 = c0 * 0.5f * (1.f + erff(c0 * 0.70710678118654752f));
                c1 = c1 * 0.5f * (1.f + erff(c1 * 0.70710678118654752f));
                c2 = c2 * 0.5f * (1.f + erff(c2 * 0.70710678118654752f));
                c3 = c3 * 0.5f * (1.f + erff(c3 * 0.70710678118654752f));
            }
            if (EPI == 0 || EPI == 1) {
                __nv_bfloat16* out = (__nv_bfloat16*)outv;
                *(uint32_t*)(out + (size_t)mA * Nc + col)       = pack2(c0, c1);
                *(uint32_t*)(out + (size_t)(mA + 8) * Nc + col) = pack2(c2, c3);
            } else {
                float* out = (float*)outv;
                float2 r0 = *(const float2*)(residual + (size_t)dstA * Nc + col);
                float2 r1 = *(const float2*)(residual + (size_t)dstB * Nc + col);
                *(float2*)(out + (size_t)dstA * Nc + col) = make_float2(c0 + r0.x, c1 + r0.y);
                *(float2*)(out + (size_t)dstB * Nc + col) = make_float2(c2 + r1.x, c3 + r1.y);
            }
        }
    }
}

// ---------------------------------------------------------------------------
// Fused-window attention (R11): one block per window, 256 threads, warp=head.
// ---------------------------------------------------------------------------
#define AQ_STR 40
#define AV_STR 72
#define ATTN_QS   0
#define ATTN_KB   (8 * 64 * AQ_STR)
#define ATTN_VT   (ATTN_KB + 8 * 64 * AQ_STR)
#define ATTN_SMEM ((ATTN_VT + 8 * 32 * AV_STR) * 2)

__global__ __launch_bounds__(256) void attn_kernel(
    const __nv_bfloat16* __restrict__ qkv,
    const float* __restrict__ attn_mask,
    const float* __restrict__ battn,
    const float* __restrict__ temperature,
    __nv_bfloat16* __restrict__ o)
{
    extern __shared__ __align__(16) __nv_bfloat16 sm[];
    const int wi = blockIdx.x;
    const int tid = threadIdx.x;
    const int h = tid >> 5, lane = tid & 31;

    const float scale = expf(temperature[0]);
    const __nv_bfloat16* base = qkv + (size_t)wi * NSEQ * 768;

    {
        uint4 z = make_uint4(0, 0, 0, 0);
        uint4* v = (uint4*)(sm + ATTN_VT);
        for (int i = tid; i < 8 * 32 * AV_STR / 8; i += 256) v[i] = z;
    }
    for (int idx = tid; idx < NSEQ * 96; idx += 256) {
        int r = idx / 96, u = idx - r * 96;
        int c0 = u * 8;
        uint4 val = *(const uint4*)(base + (size_t)r * 768 + c0);
        int ten = c0 >> 8;
        int within = c0 & 255;
        int hh = within >> 5, d = within & 31;
        if (ten == 0) {
            *(uint4*)(sm + ATTN_QS + hh * 64 * AQ_STR + r * AQ_STR + d) = val;
        } else if (ten == 1) {
            *(uint4*)(sm + ATTN_KB + hh * 64 * AQ_STR + r * AQ_STR + d) = val;
        } else {
            const __nv_bfloat16* e = (const __nv_bfloat16*)&val;
            __nv_bfloat16* vt = sm + ATTN_VT + hh * 32 * AV_STR;
            #pragma unroll
            for (int j = 0; j < 8; j++) vt[(d + j) * AV_STR + r] = e[j];
        }
    }
    __syncthreads();

    const uint32_t qB = smem_u32(sm + ATTN_QS + h * 64 * AQ_STR);
    const uint32_t kB = smem_u32(sm + ATTN_KB + h * 64 * AQ_STR);
    const uint32_t vB = smem_u32(sm + ATTN_VT + h * 32 * AV_STR);

    const uint32_t aRow = (uint32_t)(lane & 15);
    const uint32_t aKH  = (lane & 16) ? 8u : 0u;
    const uint32_t bRow = (uint32_t)((lane & 7) + ((lane & 16) ? 8 : 0));
    const uint32_t bKH  = (lane & 8) ? 8u : 0u;

    float acc[4][8][4];
    #pragma unroll
    for (int i = 0; i < 4; i++)
        #pragma unroll
        for (int j = 0; j < 8; j++)
            #pragma unroll
            for (int t = 0; t < 4; t++) acc[i][j][t] = 0.f;

    #pragma unroll
    for (int ks = 0; ks < 2; ks++) {
        uint32_t af[4][4], bf[4][4];
        #pragma unroll
        for (int am = 0; am < 4; am++)
            ldsm4(af[am], qB + ((aRow + am * 16) * AQ_STR + ks * 16 + aKH) * 2);
        #pragma unroll
        for (int g = 0; g < 4; g++)
            ldsm4(bf[g], kB + ((bRow + g * 16) * AQ_STR + ks * 16 + bKH) * 2);
        #pragma unroll
        for (int am = 0; am < 4; am++)
            #pragma unroll
            for (int nn = 0; nn < 8; nn++)
                mma16816(acc[am][nn], af[am], &bf[nn >> 1][(nn & 1) * 2]);
    }

    const float* bia = battn + h * (NSEQ * NSEQ);
    const float* msk = attn_mask + (wi & 63) * (NSEQ * NSEQ);
    const float NEG = -3.402823466e38f;
    const int qlane = lane & 3;
    uint32_t afP[4][4][4];

    #pragma unroll
    for (int am = 0; am < 4; am++) {
        #pragma unroll
        for (int half = 0; half < 2; half++) {
            int row = am * 16 + (lane >> 2) + half * 8;
            bool rv = row < NSEQ;
            float e[16];
            float mx = NEG;
            #pragma unroll
            for (int nt = 0; nt < 8; nt++) {
                #pragma unroll
                for (int j = 0; j < 2; j++) {
                    int col = nt * 8 + qlane * 2 + j;
                    float s = NEG;
                    if (rv && col < NSEQ && col != row)
                        s = acc[am][nt][half * 2 + j] * scale
                          + bia[row * NSEQ + col] + msk[row * NSEQ + col];
                    e[nt * 2 + j] = s;
                    mx = fmaxf(mx, s);
                }
            }
            mx = fmaxf(mx, __shfl_xor_sync(0xffffffffu, mx, 1));
            mx = fmaxf(mx, __shfl_xor_sync(0xffffffffu, mx, 2));
            float sum = 0.f;
            #pragma unroll
            for (int i = 0; i < 16; i++) { e[i] = fexp(e[i] - mx); sum += e[i]; }
            sum += __shfl_xor_sync(0xffffffffu, sum, 1);
            sum += __shfl_xor_sync(0xffffffffu, sum, 2);
            float inv = 1.f / sum;
            #pragma unroll
            for (int ks = 0; ks < 4; ks++) {
                uint32_t lo = pack2(e[4 * ks] * inv,     e[4 * ks + 1] * inv);
                uint32_t hi = pack2(e[4 * ks + 2] * inv, e[4 * ks + 3] * inv);
                afP[am][ks][half]     = lo;
                afP[am][ks][2 + half] = hi;
            }
        }
    }

    float accP[4][4][4];
    #pragma unroll
    for (int i = 0; i < 4; i++)
        #pragma unroll
        for (int j = 0; j < 4; j++)
            #pragma unroll
            for (int t = 0; t < 4; t++) accP[i][j][t] = 0.f;

    #pragma unroll
    for (int ks = 0; ks < 4; ks++) {
        uint32_t bf[2][4];
        #pragma unroll
        for (int g = 0; g < 2; g++)
            ldsm4(bf[g], vB + ((bRow + g * 16) * AV_STR + ks * 16 + bKH) * 2);
        #pragma unroll
        for (int am = 0; am < 4; am++)
            #pragma unroll
            for (int nn = 0; nn < 4; nn++)
                mma16816(accP[am][nn], afP[am][ks], &bf[nn >> 1][(nn & 1) * 2]);
    }

    #pragma unroll
    for (int am = 0; am < 4; am++) {
        int n = am * 16 + (lane >> 2);
        int d0 = qlane * 2;
        #pragma unroll
        for (int nn = 0; nn < 4; nn++) {
            int d = d0 + nn * 8;
            if (n < NSEQ)
                *(uint32_t*)(o + (size_t)(wi * NSEQ + n) * C_DIM + h * HDIM + d)
                    = pack2(accP[am][nn][0], accP[am][nn][1]);
            if (n + 8 < NSEQ)
                *(uint32_t*)(o + (size_t)(wi * NSEQ + n + 8) * C_DIM + h * HDIM + d)
                    = pack2(accP[am][nn][2], accP[am][nn][3]);
        }
    }
}

// ---------------------------------------------------------------------------
#define GEMM_SMEM (4 * STAGE_B)

extern "C" void kernel_launch(void* const* d_in, const int* in_sizes, int n_in,
                              void* d_out, int out_size)
{
    const float* x        = (const float*)d_in[0];
    const float* attn_msk = (const float*)d_in[1];
    const float* norm1_g  = (const float*)d_in[2];
    const float* norm1_b  = (const float*)d_in[3];
    const float* qkv_w    = (const float*)d_in[4];
    const float* qkv_b    = (const float*)d_in[5];
    const float* temp     = (const float*)d_in[6];
    const float* rel_tab  = (const float*)d_in[7];
    const float* proj_w   = (const float*)d_in[8];
    const float* proj_b   = (const float*)d_in[9];
    const float* norm2_g  = (const float*)d_in[10];
    const float* norm2_b  = (const float*)d_in[11];
    const float* fc1_w    = (const float*)d_in[12];
    const float* fc1_b    = (const float*)d_in[13];
    const float* fc2_w    = (const float*)d_in[14];
    const float* fc2_b    = (const float*)d_in[15];
    const int*   rel_idx  = (const int*)d_in[16];
    float* out = (float*)d_out;

    __nv_bfloat16 *zw, *qkv, *o, *hbuf, *fc1, *wqkvT, *wprojT, *wfc1T, *wfc2T;
    float *x2, *battn;
    cudaGetSymbolAddress((void**)&zw,    g_zw);
    cudaGetSymbolAddress((void**)&qkv,   g_qkv);
    cudaGetSymbolAddress((void**)&o,     g_o);
    cudaGetSymbolAddress((void**)&x2,    g_x2);
    cudaGetSymbolAddress((void**)&hbuf,  g_h);
    cudaGetSymbolAddress((void**)&fc1,   g_fc1);
    cudaGetSymbolAddress((void**)&wqkvT, g_wqkvT);
    cudaGetSymbolAddress((void**)&wprojT,g_wprojT);
    cudaGetSymbolAddress((void**)&wfc1T, g_wfc1T);
    cudaGetSymbolAddress((void**)&wfc2T, g_wfc2T);
    cudaGetSymbolAddress((void**)&battn, g_battn);

    static bool attr_done = false;
    if (!attr_done) {
        cudaFuncSetAttribute(gemm_bf16<0>, cudaFuncAttributeMaxDynamicSharedMemorySize, GEMM_SMEM);
        cudaFuncSetAttribute(gemm_bf16<1>, cudaFuncAttributeMaxDynamicSharedMemorySize, GEMM_SMEM);
        cudaFuncSetAttribute(gemm_bf16<2>, cudaFuncAttributeMaxDynamicSharedMemorySize, GEMM_SMEM);
        cudaFuncSetAttribute(gemm_bf16<3>, cudaFuncAttributeMaxDynamicSharedMemorySize, GEMM_SMEM);
        cudaFuncSetAttribute(attn_kernel, cudaFuncAttributeMaxDynamicSharedMemorySize, ATTN_SMEM);
        attr_done = true;
    }

    wconv_kernel<<<(256 * 768 + 255) / 256, 256>>>(qkv_w, wqkvT, 256, 768);          // 0
    ln_kernel<<<M_TOK / 8, 256>>>(x, norm1_g, norm1_b, zw, 1);                        // 1
    bias_kernel<<<(NHEADS * NSEQ * NSEQ + 255) / 256, 256>>>(rel_tab, rel_idx, battn);// 2
    gemm_bf16<0><<<dim3(3, M_TOK / 128), 256, GEMM_SMEM>>>(zw, wqkvT, qkv_b, nullptr, qkv, 256, 768); // 3
    wconv_kernel<<<(256 * 256 + 255) / 256, 256>>>(proj_w, wprojT, 256, 256);         // 4
    wconv_kernel<<<(256 * 1024 + 255) / 256, 256>>>(fc1_w, wfc1T, 256, 1024);         // 5
    wconv_kernel<<<(1024 * 256 + 255) / 256, 256>>>(fc2_w, wfc2T, 1024, 256);         // 6
    attn_kernel<<<NWIN, 256, ATTN_SMEM>>>(qkv, attn_msk, battn, temp, o);             // 7
    gemm_bf16<3><<<dim3(1, M_TOK / 128), 256, GEMM_SMEM>>>(o, wprojT, proj_b, x, x2, 256, 256); // 8
    ln_kernel<<<M_TOK / 8, 256>>>(x2, norm2_g, norm2_b, hbuf, 0);                     // 9
    gemm_bf16<1><<<dim3(4, M_TOK / 128), 256, GEMM_SMEM>>>(hbuf, wfc1T, fc1_b, nullptr, fc1, 256, 1024); // 10
    gemm_bf16<2><<<dim3(1, M_TOK / 128), 256, GEMM_SMEM>>>(fc1, wfc2T, fc2_b, x2, out, 1024, 256);       // 11
}

// round 13
// speedup vs baseline: 1.1597x; 1.1597x over previous
#include <cuda_runtime.h>
#include <cuda_bf16.h>
#include <math.h>
#include <stdint.h>

// ---------------------------------------------------------------------------
// SwinTransformerBlock on GB300: persistent B-panel bf16 GEMMs + fused attn
// B=32, H=W=56, C=256, NH=8, hd=32, WS=7, SS=3
// ---------------------------------------------------------------------------

#define M_TOK   100352
#define C_DIM   256
#define NHEADS  8
#define HDIM    32
#define NWIN    2048
#define NSEQ    49
#define NMT     784            // M_TOK / 128

__device__ __nv_bfloat16 g_zw [(size_t)M_TOK * C_DIM];
__device__ __nv_bfloat16 g_qkv[(size_t)M_TOK * 768];
__device__ __nv_bfloat16 g_o  [(size_t)M_TOK * C_DIM];
__device__ float         g_x2 [(size_t)M_TOK * C_DIM];
__device__ __nv_bfloat16 g_h  [(size_t)M_TOK * C_DIM];
__device__ __nv_bfloat16 g_fc1[(size_t)M_TOK * 1024];
__device__ __nv_bfloat16 g_wqkvT[768 * 256];
__device__ __nv_bfloat16 g_wprojT[256 * 256];
__device__ __nv_bfloat16 g_wfc1T[1024 * 256];
__device__ __nv_bfloat16 g_wfc2T[256 * 1024];
__device__ float g_battn[NHEADS * NSEQ * NSEQ];

// ---------------------------------------------------------------------------
__device__ __forceinline__ uint32_t smem_u32(const void* p) {
    uint32_t a;
    asm("{ .reg .u64 t; cvta.to.shared.u64 t, %1; cvt.u32.u64 %0, t; }" : "=r"(a) : "l"(p));
    return a;
}
__device__ __forceinline__ void ldsm4(uint32_t* r, uint32_t addr) {
    asm volatile("ldmatrix.sync.aligned.m8n8.x4.shared.b16 {%0,%1,%2,%3}, [%4];"
                 : "=r"(r[0]), "=r"(r[1]), "=r"(r[2]), "=r"(r[3]) : "r"(addr));
}
__device__ __forceinline__ void mma16816(float* c, const uint32_t* a, const uint32_t* b) {
    asm volatile(
        "mma.sync.aligned.m16n8k16.row.col.f32.bf16.bf16.f32 "
        "{%0,%1,%2,%3}, {%4,%5,%6,%7}, {%8,%9}, {%0,%1,%2,%3};"
        : "+f"(c[0]), "+f"(c[1]), "+f"(c[2]), "+f"(c[3])
        : "r"(a[0]), "r"(a[1]), "r"(a[2]), "r"(a[3]), "r"(b[0]), "r"(b[1]));
}
__device__ __forceinline__ uint32_t pack2(float a, float b) {
    __nv_bfloat162 h = __floats2bfloat162_rn(a, b);
    return *(uint32_t*)&h;
}
__device__ __forceinline__ float fexp(float x) {
    float z = fmaxf(x * 1.4426950408889634f, -126.0f);
    float t = z + 12582912.0f;
    int   i = __float_as_int(t) - 0x4B400000;
    float f = z - (t - 12582912.0f);
    float p = 0.00961804886f;
    p = fmaf(p, f, 0.05550410866f);
    p = fmaf(p, f, 0.24022650696f);
    p = fmaf(p, f, 0.69314718056f);
    p = fmaf(p, f, 1.0f);
    return __int_as_float(__float_as_int(p) + (i << 23));
}
#define CP16(dst, src) asm volatile("cp.async.cg.shared.global [%0], [%1], 16;" :: "r"(dst), "l"(src))
#define CP_COMMIT()    asm volatile("cp.async.commit_group;" ::: "memory")
#define CP_WAIT0()     asm volatile("cp.async.wait_group 0;" ::: "memory")
#define CP_WAIT2()     asm volatile("cp.async.wait_group 2;" ::: "memory")

// ---------------------------------------------------------------------------
__global__ void wconv_kernel(const float* __restrict__ in, __nv_bfloat16* __restrict__ out,
                             int K, int N)
{
    int id = blockIdx.x * 256 + threadIdx.x;
    if (id >= K * N) return;
    int n = id / K, k = id - n * K;
    out[id] = __float2bfloat16(in[(size_t)k * N + n]);
}

__global__ void bias_kernel(const float* __restrict__ rel_table,
                            const int* __restrict__ rel_idx,
                            float* __restrict__ out)
{
    int idx = blockIdx.x * 256 + threadIdx.x;
    if (idx >= NHEADS * NSEQ * NSEQ) return;
    int h = idx / (NSEQ * NSEQ), nm = idx % (NSEQ * NSEQ);
    out[idx] = rel_table[rel_idx[nm] * NHEADS + h];
}

// ---------------------------------------------------------------------------
// LayerNorm: warp-per-token. 8 tokens / block.
// ---------------------------------------------------------------------------
__global__ __launch_bounds__(256) void ln_kernel(
    const float* __restrict__ x,
    const float* __restrict__ gamma,
    const float* __restrict__ beta,
    __nv_bfloat16* __restrict__ out,
    int shifted)
{
    int wid = threadIdx.x >> 5, lane = threadIdx.x & 31;
    int t = blockIdx.x * 8 + wid;
    int src;
    if (shifted) {
        int wi  = t / NSEQ;
        int pos = t - wi * NSEQ;
        int b    = wi >> 6;
        int wrem = wi & 63;
        int hs = (wrem >> 3) * 7 + pos / 7;
        int ws = (wrem & 7) * 7 + pos % 7;
        int sh = hs + 3; if (sh >= 56) sh -= 56;
        int sw = ws + 3; if (sw >= 56) sw -= 56;
        src = b * 3136 + sh * 56 + sw;
    } else {
        src = t;
    }
    const float* row = x + (size_t)src * C_DIM + lane * 8;
    float4 v0 = *(const float4*)(row);
    float4 v1 = *(const float4*)(row + 4);
    float v[8] = {v0.x, v0.y, v0.z, v0.w, v1.x, v1.y, v1.z, v1.w};
    float s = 0.f, s2 = 0.f;
    #pragma unroll
    for (int i = 0; i < 8; i++) { s += v[i]; s2 += v[i] * v[i]; }
    #pragma unroll
    for (int off = 16; off; off >>= 1) {
        s  += __shfl_xor_sync(0xffffffffu, s,  off);
        s2 += __shfl_xor_sync(0xffffffffu, s2, off);
    }
    float mean = s * (1.f / 256.f);
    float var  = s2 * (1.f / 256.f) - mean * mean;
    float r = rsqrtf(var + 1e-6f);
    const float* g4 = gamma + lane * 8;
    const float* b4 = beta + lane * 8;
    uint32_t o4[4];
    #pragma unroll
    for (int i = 0; i < 4; i++) {
        float a0 = (v[2*i]   - mean) * r * g4[2*i]   + b4[2*i];
        float a1 = (v[2*i+1] - mean) * r * g4[2*i+1] + b4[2*i+1];
        o4[i] = pack2(a0, a1);
    }
    *(uint4*)(out + (size_t)t * C_DIM + lane * 8) = *(uint4*)o4;
}

// ---------------------------------------------------------------------------
// Shared epilogue (both GEMM kernels): per 64x64 warp tile.
// ---------------------------------------------------------------------------
template<int EPI>
__device__ __forceinline__ void gemm_epilogue(
    float acc[4][8][4], const float* sbias, const float* residual,
    void* outv, int Nc, int bm, int bn, int wm, int wn, int lane)
{
    const int n0 = bn + wn * 64 + (lane & 3) * 2;
    const int m0 = bm + wm * 64 + (lane >> 2);

    #pragma unroll
    for (int am = 0; am < 4; am++) {
        int mA = m0 + am * 16;
        int dstA = mA, dstB = mA + 8;
        if (EPI == 3) {
            #pragma unroll
            for (int h = 0; h < 2; h++) {
                int m = mA + h * 8;
                int wi  = m / NSEQ;
                int pos = m - wi * NSEQ;
                int b    = wi >> 6;
                int wrem = wi & 63;
                int hs = (wrem >> 3) * 7 + pos / 7;
                int ws = (wrem & 7) * 7 + pos % 7;
                int dh = hs + 3; if (dh >= 56) dh -= 56;
                int dw = ws + 3; if (dw >= 56) dw -= 56;
                int d = b * 3136 + dh * 56 + dw;
                if (h == 0) dstA = d; else dstB = d;
            }
        }
        #pragma unroll
        for (int nn = 0; nn < 8; nn++) {
            int col = n0 + nn * 8;
            float b0 = sbias[col - bn], b1 = sbias[col - bn + 1];
            float c0 = acc[am][nn][0] + b0, c1 = acc[am][nn][1] + b1;
            float c2 = acc[am][nn][2] + b0, c3 = acc[am][nn][3] + b1;
            if (EPI == 1) {
                c0 = c0 * 0.5f * (1.f + erff(c0 * 0.70710678118654752f));
                c1 = c1 * 0.5f * (1.f + erff(c1 * 0.70710678118654752f));
                c2 = c2 * 0.5f * (1.f + erff(c2 * 0.70710678118654752f));
                c3 = c3 * 0.5f * (1.f + erff(c3 * 0.70710678118654752f));
            }
            if (EPI == 0 || EPI == 1) {
                __nv_bfloat16* out = (__nv_bfloat16*)outv;
                *(uint32_t*)(out + (size_t)mA * Nc + col)       = pack2(c0, c1);
                *(uint32_t*)(out + (size_t)(mA + 8) * Nc + col) = pack2(c2, c3);
            } else {
                float* out = (float*)outv;
                float2 r0 = *(const float2*)(residual + (size_t)dstA * Nc + col);
                float2 r1 = *(const float2*)(residual + (size_t)dstB * Nc + col);
                *(float2*)(out + (size_t)dstA * Nc + col) = make_float2(c0 + r0.x, c1 + r0.y);
                *(float2*)(out + (size_t)dstB * Nc + col) = make_float2(c2 + r1.x, c3 + r1.y);
            }
        }
    }
}

// ---------------------------------------------------------------------------
// Persistent B-panel GEMM (K=256 only): tile 128x128, 128 threads,
// 64x64 warp tiles. B panel (8 chunk-tiles, 80KB) resident; A 2-stage stream.
// grid = (Nc/128, GY); CTA owns bn, loops mt = by, by+GY, ...
// ---------------------------------------------------------------------------
#define KP 40
#define BCH (128 * KP * 2)            // 10240 B per chunk-tile
#define PB_SMEM (8 * BCH + 2 * BCH)   // 102400

template<int EPI>
__global__ __launch_bounds__(128) void gemm_pb(
    const __nv_bfloat16* __restrict__ A,
    const __nv_bfloat16* __restrict__ Bt,
    const float* __restrict__ bias,
    const float* __restrict__ residual,
    void* __restrict__ outv,
    int Nc)
{
    extern __shared__ __align__(16) uint8_t smem[];
    __shared__ float sbias[128];

    const int tid = threadIdx.x;
    const int lane = tid & 31, wid = tid >> 5;
    const int wm = wid & 1;
    const int wn = wid >> 1;
    const int bn = blockIdx.x * 128;
    const int GY = gridDim.y;

    sbias[tid] = bias[bn + tid];

    const uint32_t sBase = smem_u32(smem);
    const uint32_t aBase = sBase + 8 * BCH;

    const int lr = tid >> 2;            // 0..31
    const int lc = (tid & 3) * 8;

    // B panel: 8 chunk-tiles, one commit group
    {
        const __nv_bfloat16* Bb = Bt + (size_t)bn * 256;
        #pragma unroll
        for (int ch = 0; ch < 8; ch++)
            #pragma unroll
            for (int j = 0; j < 4; j++) {
                int r = lr + j * 32;
                CP16(sBase + ch * BCH + (uint32_t)(r * KP + lc) * 2,
                     Bb + (size_t)r * 256 + ch * 32 + lc);
            }
        CP_COMMIT();
    }
    // first A chunk (tile by, chunk 0) -> stage 0
    {
        const __nv_bfloat16* Ab = A + (size_t)blockIdx.y * 128 * 256;
        #pragma unroll
        for (int j = 0; j < 4; j++) {
            int r = lr + j * 32;
            CP16(aBase + (uint32_t)(r * KP + lc) * 2, Ab + (size_t)r * 256 + lc);
        }
        CP_COMMIT();
    }

    const uint32_t aRowB = (uint32_t)(wm * 64 + (lane & 15));
    const uint32_t aKH   = (lane & 16) ? 8u : 0u;
    const uint32_t bRowB = (uint32_t)(wn * 64 + (lane & 7) + ((lane & 16) ? 8 : 0));
    const uint32_t bKH   = (lane & 8) ? 8u : 0u;

    float acc[4][8][4];
    #pragma unroll
    for (int i = 0; i < 4; i++)
        #pragma unroll
        for (int j = 0; j < 8; j++)
            #pragma unroll
            for (int t = 0; t < 4; t++) acc[i][j][t] = 0.f;

    const int nTiles = (NMT - blockIdx.y + GY - 1) / GY;
    const int T = nTiles * 8;

    for (int g = 0; g < T; g++) {
        int kc = g & 7;
        CP_WAIT0();
        __syncthreads();

        // prefetch chunk g+1 into stage (g+1)&1
        if (g + 1 < T) {
            int g1 = g + 1;
            int mt1 = blockIdx.y + (g1 >> 3) * GY;
            int kc1 = g1 & 7;
            const __nv_bfloat16* Ab = A + (size_t)mt1 * 128 * 256 + kc1 * 32;
            uint32_t st = aBase + (uint32_t)(g1 & 1) * BCH;
            #pragma unroll
            for (int j = 0; j < 4; j++) {
                int r = lr + j * 32;
                CP16(st + (uint32_t)(r * KP + lc) * 2, Ab + (size_t)r * 256 + lc);
            }
        }
        CP_COMMIT();

        const uint32_t aS = aBase + (uint32_t)(g & 1) * BCH;
        const uint32_t bS = sBase + (uint32_t)kc * BCH;
        #pragma unroll
        for (int ks = 0; ks < 2; ks++) {
            uint32_t af[4][4], bf[4][4];
            #pragma unroll
            for (int am = 0; am < 4; am++)
                ldsm4(af[am], aS + ((aRowB + am * 16) * KP + ks * 16 + aKH) * 2);
            #pragma unroll
            for (int gi = 0; gi < 4; gi++)
                ldsm4(bf[gi], bS + ((bRowB + gi * 16) * KP + ks * 16 + bKH) * 2);
            #pragma unroll
            for (int am = 0; am < 4; am++)
                #pragma unroll
                for (int nn = 0; nn < 8; nn++)
                    mma16816(acc[am][nn], af[am], &bf[nn >> 1][(nn & 1) * 2]);
        }

        if (kc == 7) {
            int bm = (blockIdx.y + (g >> 3) * GY) * 128;
            gemm_epilogue<EPI>(acc, sbias, residual, outv, Nc, bm, bn, wm, wn, lane);
            #pragma unroll
            for (int i = 0; i < 4; i++)
                #pragma unroll
                for (int j = 0; j < 8; j++)
                    #pragma unroll
                    for (int t = 0; t < 4; t++) acc[i][j][t] = 0.f;
        }
    }
}

// ---------------------------------------------------------------------------
// Streaming GEMM (R8 config) for fc2 (K=1024): tile 128x128, BK=32,
// 128 threads, 64x64 warp tiles, 4-stage cp.async.
// ---------------------------------------------------------------------------
#define STAGE_B (2 * BCH)
#define B_OFF   BCH
#define ST_SMEM (4 * STAGE_B)

template<int EPI>
__global__ __launch_bounds__(128) void gemm_st(
    const __nv_bfloat16* __restrict__ A,
    const __nv_bfloat16* __restrict__ Bt,
    const float* __restrict__ bias,
    const float* __restrict__ residual,
    void* __restrict__ outv,
    int K, int Nc)
{
    extern __shared__ __align__(16) uint8_t smem[];
    __shared__ float sbias[128];

    const int tid = threadIdx.x;
    const int lane = tid & 31, wid = tid >> 5;
    const int wm = wid & 1;
    const int wn = wid >> 1;
    const int bn = blockIdx.x * 128, bm = blockIdx.y * 128;

    sbias[tid] = bias[bn + tid];

    const uint32_t sBase = smem_u32(smem);

    const int ldr0 = tid >> 2;
    const int ldc  = (tid & 3) * 8;

    const uint32_t aRowB = (uint32_t)(wm * 64 + (lane & 15));
    const uint32_t aKH   = (lane & 16) ? 8u : 0u;
    const uint32_t bRowB = (uint32_t)(wn * 64 + (lane & 7) + ((lane & 16) ? 8 : 0));
    const uint32_t bKH   = (lane & 8) ? 8u : 0u;

    float acc[4][8][4];
    #pragma unroll
    for (int i = 0; i < 4; i++)
        #pragma unroll
        for (int j = 0; j < 8; j++)
            #pragma unroll
            for (int t = 0; t < 4; t++) acc[i][j][t] = 0.f;

    const int nk = K >> 5;

    #pragma unroll
    for (int s = 0; s < 3; s++) {
        uint32_t st = sBase + s * STAGE_B;
        const __nv_bfloat16* Ab = A + (size_t)bm * K + s * 32;
        const __nv_bfloat16* Bb = Bt + (size_t)bn * K + s * 32;
        #pragma unroll
        for (int j = 0; j < 4; j++) {
            int r = ldr0 + j * 32;
            CP16(st + (uint32_t)(r * KP + ldc) * 2,         Ab + (size_t)r * K + ldc);
            CP16(st + B_OFF + (uint32_t)(r * KP + ldc) * 2, Bb + (size_t)r * K + ldc);
        }
        CP_COMMIT();
    }

    for (int kc = 0; kc < nk; kc++) {
        CP_WAIT2();
        __syncthreads();

        if (kc + 3 < nk) {
            uint32_t st = sBase + ((kc + 3) & 3) * STAGE_B;
            const __nv_bfloat16* Ab = A + (size_t)bm * K + (kc + 3) * 32;
            const __nv_bfloat16* Bb = Bt + (size_t)bn * K + (kc + 3) * 32;
            #pragma unroll
            for (int j = 0; j < 4; j++) {
                int r = ldr0 + j * 32;
                CP16(st + (uint32_t)(r * KP + ldc) * 2,         Ab + (size_t)r * K + ldc);
                CP16(st + B_OFF + (uint32_t)(r * KP + ldc) * 2, Bb + (size_t)r * K + ldc);
            }
        }
        CP_COMMIT();

        const uint32_t aS = sBase + (kc & 3) * STAGE_B;
        const uint32_t bS = aS + B_OFF;
        #pragma unroll
        for (int ks = 0; ks < 2; ks++) {
            uint32_t af[4][4], bf[4][4];
            #pragma unroll
            for (int am = 0; am < 4; am++)
                ldsm4(af[am], aS + ((aRowB + am * 16) * KP + ks * 16 + aKH) * 2);
            #pragma unroll
            for (int g = 0; g < 4; g++)
                ldsm4(bf[g], bS + ((bRowB + g * 16) * KP + ks * 16 + bKH) * 2);
            #pragma unroll
            for (int am = 0; am < 4; am++)
                #pragma unroll
                for (int nn = 0; nn < 8; nn++)
                    mma16816(acc[am][nn], af[am], &bf[nn >> 1][(nn & 1) * 2]);
        }
    }

    gemm_epilogue<EPI>(acc, sbias, residual, outv, Nc, bm, bn, wm, wn, lane);
}

// ---------------------------------------------------------------------------
// Fused-window attention (R11): one block per window, 256 threads, warp=head.
// ---------------------------------------------------------------------------
#define AQ_STR 40
#define AV_STR 72
#define ATTN_QS   0
#define ATTN_KB   (8 * 64 * AQ_STR)
#define ATTN_VT   (ATTN_KB + 8 * 64 * AQ_STR)
#define ATTN_SMEM ((ATTN_VT + 8 * 32 * AV_STR) * 2)

__global__ __launch_bounds__(256) void attn_kernel(
    const __nv_bfloat16* __restrict__ qkv,
    const float* __restrict__ attn_mask,
    const float* __restrict__ battn,
    const float* __restrict__ temperature,
    __nv_bfloat16* __restrict__ o)
{
    extern __shared__ __align__(16) __nv_bfloat16 sm[];
    const int wi = blockIdx.x;
    const int tid = threadIdx.x;
    const int h = tid >> 5, lane = tid & 31;

    const float scale = expf(temperature[0]);
    const __nv_bfloat16* base = qkv + (size_t)wi * NSEQ * 768;

    {
        uint4 z = make_uint4(0, 0, 0, 0);
        uint4* v = (uint4*)(sm + ATTN_VT);
        for (int i = tid; i < 8 * 32 * AV_STR / 8; i += 256) v[i] = z;
    }
    for (int idx = tid; idx < NSEQ * 96; idx += 256) {
        int r = idx / 96, u = idx - r * 96;
        int c0 = u * 8;
        uint4 val = *(const uint4*)(base + (size_t)r * 768 + c0);
        int ten = c0 >> 8;
        int within = c0 & 255;
        int hh = within >> 5, d = within & 31;
        if (ten == 0) {
            *(uint4*)(sm + ATTN_QS + hh * 64 * AQ_STR + r * AQ_STR + d) = val;
        } else if (ten == 1) {
            *(uint4*)(sm + ATTN_KB + hh * 64 * AQ_STR + r * AQ_STR + d) = val;
        } else {
            const __nv_bfloat16* e = (const __nv_bfloat16*)&val;
            __nv_bfloat16* vt = sm + ATTN_VT + hh * 32 * AV_STR;
            #pragma unroll
            for (int j = 0; j < 8; j++) vt[(d + j) * AV_STR + r] = e[j];
        }
    }
    __syncthreads();

    const uint32_t qB = smem_u32(sm + ATTN_QS + h * 64 * AQ_STR);
    const uint32_t kB = smem_u32(sm + ATTN_KB + h * 64 * AQ_STR);
    const uint32_t vB = smem_u32(sm + ATTN_VT + h * 32 * AV_STR);

    const uint32_t aRow = (uint32_t)(lane & 15);
    const uint32_t aKH  = (lane & 16) ? 8u : 0u;
    const uint32_t bRow = (uint32_t)((lane & 7) + ((lane & 16) ? 8 : 0));
    const uint32_t bKH  = (lane & 8) ? 8u : 0u;

    float acc[4][8][4];
    #pragma unroll
    for (int i = 0; i < 4; i++)
        #pragma unroll
        for (int j = 0; j < 8; j++)
            #pragma unroll
            for (int t = 0; t < 4; t++) acc[i][j][t] = 0.f;

    #pragma unroll
    for (int ks = 0; ks < 2; ks++) {
        uint32_t af[4][4], bf[4][4];
        #pragma unroll
        for (int am = 0; am < 4; am++)
            ldsm4(af[am], qB + ((aRow + am * 16) * AQ_STR + ks * 16 + aKH) * 2);
        #pragma unroll
        for (int g = 0; g < 4; g++)
            ldsm4(bf[g], kB + ((bRow + g * 16) * AQ_STR + ks * 16 + bKH) * 2);
        #pragma unroll
        for (int am = 0; am < 4; am++)
            #pragma unroll
            for (int nn = 0; nn < 8; nn++)
                mma16816(acc[am][nn], af[am], &bf[nn >> 1][(nn & 1) * 2]);
    }

    const float* bia = battn + h * (NSEQ * NSEQ);
    const float* msk = attn_mask + (wi & 63) * (NSEQ * NSEQ);
    const float NEG = -3.402823466e38f;
    const int qlane = lane & 3;
    uint32_t afP[4][4][4];

    #pragma unroll
    for (int am = 0; am < 4; am++) {
        #pragma unroll
        for (int half = 0; half < 2; half++) {
            int row = am * 16 + (lane >> 2) + half * 8;
            bool rv = row < NSEQ;
            float e[16];
            float mx = NEG;
            #pragma unroll
            for (int nt = 0; nt < 8; nt++) {
                #pragma unroll
                for (int j = 0; j < 2; j++) {
                    int col = nt * 8 + qlane * 2 + j;
                    float s = NEG;
                    if (rv && col < NSEQ && col != row)
                        s = acc[am][nt][half * 2 + j] * scale
                          + bia[row * NSEQ + col] + msk[row * NSEQ + col];
                    e[nt * 2 + j] = s;
                    mx = fmaxf(mx, s);
                }
            }
            mx = fmaxf(mx, __shfl_xor_sync(0xffffffffu, mx, 1));
            mx = fmaxf(mx, __shfl_xor_sync(0xffffffffu, mx, 2));
            float sum = 0.f;
            #pragma unroll
            for (int i = 0; i < 16; i++) { e[i] = fexp(e[i] - mx); sum += e[i]; }
            sum += __shfl_xor_sync(0xffffffffu, sum, 1);
            sum += __shfl_xor_sync(0xffffffffu, sum, 2);
            float inv = 1.f / sum;
            #pragma unroll
            for (int ks = 0; ks < 4; ks++) {
                uint32_t lo = pack2(e[4 * ks] * inv,     e[4 * ks + 1] * inv);
                uint32_t hi = pack2(e[4 * ks + 2] * inv, e[4 * ks + 3] * inv);
                afP[am][ks][half]     = lo;
                afP[am][ks][2 + half] = hi;
            }
        }
    }

    float accP[4][4][4];
    #pragma unroll
    for (int i = 0; i < 4; i++)
        #pragma unroll
        for (int j = 0; j < 4; j++)
            #pragma unroll
            for (int t = 0; t < 4; t++) accP[i][j][t] = 0.f;

    #pragma unroll
    for (int ks = 0; ks < 4; ks++) {
        uint32_t bf[2][4];
        #pragma unroll
        for (int g = 0; g < 2; g++)
            ldsm4(bf[g], vB + ((bRow + g * 16) * AV_STR + ks * 16 + bKH) * 2);
        #pragma unroll
        for (int am = 0; am < 4; am++)
            #pragma unroll
            for (int nn = 0; nn < 4; nn++)
                mma16816(accP[am][nn], afP[am][ks], &bf[nn >> 1][(nn & 1) * 2]);
    }

    #pragma unroll
    for (int am = 0; am < 4; am++) {
        int n = am * 16 + (lane >> 2);
        int d0 = qlane * 2;
        #pragma unroll
        for (int nn = 0; nn < 4; nn++) {
            int d = d0 + nn * 8;
            if (n < NSEQ)
                *(uint32_t*)(o + (size_t)(wi * NSEQ + n) * C_DIM + h * HDIM + d)
                    = pack2(accP[am][nn][0], accP[am][nn][1]);
            if (n + 8 < NSEQ)
                *(uint32_t*)(o + (size_t)(wi * NSEQ + n + 8) * C_DIM + h * HDIM + d)
                    = pack2(accP[am][nn][2], accP[am][nn][3]);
        }
    }
}

// ---------------------------------------------------------------------------
extern "C" void kernel_launch(void* const* d_in, const int* in_sizes, int n_in,
                              void* d_out, int out_size)
{
    const float* x        = (const float*)d_in[0];
    const float* attn_msk = (const float*)d_in[1];
    const float* norm1_g  = (const float*)d_in[2];
    const float* norm1_b  = (const float*)d_in[3];
    const float* qkv_w    = (const float*)d_in[4];
    const float* qkv_b    = (const float*)d_in[5];
    const float* temp     = (const float*)d_in[6];
    const float* rel_tab  = (const float*)d_in[7];
    const float* proj_w   = (const float*)d_in[8];
    const float* proj_b   = (const float*)d_in[9];
    const float* norm2_g  = (const float*)d_in[10];
    const float* norm2_b  = (const float*)d_in[11];
    const float* fc1_w    = (const float*)d_in[12];
    const float* fc1_b    = (const float*)d_in[13];
    const float* fc2_w    = (const float*)d_in[14];
    const float* fc2_b    = (const float*)d_in[15];
    const int*   rel_idx  = (const int*)d_in[16];
    float* out = (float*)d_out;

    __nv_bfloat16 *zw, *qkv, *o, *hbuf, *fc1, *wqkvT, *wprojT, *wfc1T, *wfc2T;
    float *x2, *battn;
    cudaGetSymbolAddress((void**)&zw,    g_zw);
    cudaGetSymbolAddress((void**)&qkv,   g_qkv);
    cudaGetSymbolAddress((void**)&o,     g_o);
    cudaGetSymbolAddress((void**)&x2,    g_x2);
    cudaGetSymbolAddress((void**)&hbuf,  g_h);
    cudaGetSymbolAddress((void**)&fc1,   g_fc1);
    cudaGetSymbolAddress((void**)&wqkvT, g_wqkvT);
    cudaGetSymbolAddress((void**)&wprojT,g_wprojT);
    cudaGetSymbolAddress((void**)&wfc1T, g_wfc1T);
    cudaGetSymbolAddress((void**)&wfc2T, g_wfc2T);
    cudaGetSymbolAddress((void**)&battn, g_battn);

    static bool attr_done = false;
    if (!attr_done) {
        cudaFuncSetAttribute(gemm_pb<0>, cudaFuncAttributeMaxDynamicSharedMemorySize, PB_SMEM);
        cudaFuncSetAttribute(gemm_pb<1>, cudaFuncAttributeMaxDynamicSharedMemorySize, PB_SMEM);
        cudaFuncSetAttribute(gemm_pb<3>, cudaFuncAttributeMaxDynamicSharedMemorySize, PB_SMEM);
        cudaFuncSetAttribute(gemm_st<2>, cudaFuncAttributeMaxDynamicSharedMemorySize, ST_SMEM);
        cudaFuncSetAttribute(attn_kernel, cudaFuncAttributeMaxDynamicSharedMemorySize, ATTN_SMEM);
        attr_done = true;
    }

    wconv_kernel<<<(256 * 768 + 255) / 256, 256>>>(qkv_w, wqkvT, 256, 768);          // 0
    ln_kernel<<<M_TOK / 8, 256>>>(x, norm1_g, norm1_b, zw, 1);                        // 1
    bias_kernel<<<(NHEADS * NSEQ * NSEQ + 255) / 256, 256>>>(rel_tab, rel_idx, battn);// 2
    gemm_pb<0><<<dim3(6, 48), 128, PB_SMEM>>>(zw, wqkvT, qkv_b, nullptr, qkv, 768);   // 3
    wconv_kernel<<<(256 * 256 + 255) / 256, 256>>>(proj_w, wprojT, 256, 256);         // 4
    wconv_kernel<<<(256 * 1024 + 255) / 256, 256>>>(fc1_w, wfc1T, 256, 1024);         // 5
    wconv_kernel<<<(1024 * 256 + 255) / 256, 256>>>(fc2_w, wfc2T, 1024, 256);         // 6
    attn_kernel<<<NWIN, 256, ATTN_SMEM>>>(qkv, attn_msk, battn, temp, o);             // 7
    gemm_pb<3><<<dim3(2, 148), 128, PB_SMEM>>>(o, wprojT, proj_b, x, x2, 256);        // 8
    ln_kernel<<<M_TOK / 8, 256>>>(x2, norm2_g, norm2_b, hbuf, 0);                     // 9
    gemm_pb<1><<<dim3(8, 37), 128, PB_SMEM>>>(hbuf, wfc1T, fc1_b, nullptr, fc1, 1024);// 10
    gemm_st<2><<<dim3(2, NMT), 128, ST_SMEM>>>(fc1, wfc2T, fc2_b, x2, out, 1024, 256);// 11
}

// round 14
// speedup vs baseline: 1.1637x; 1.0034x over previous
#include <cuda_runtime.h>
#include <cuda_bf16.h>
#include <math.h>
#include <stdint.h>

// ---------------------------------------------------------------------------
// SwinTransformerBlock on GB300: persistent B-panel bf16 GEMMs + fused attn
// with fragment-ordered combined mask table.
// ---------------------------------------------------------------------------

#define M_TOK   100352
#define C_DIM   256
#define NHEADS  8
#define HDIM    32
#define NWIN    2048
#define NSEQ    49
#define NMT     784            // M_TOK / 128

__device__ __nv_bfloat16 g_zw [(size_t)M_TOK * C_DIM];
__device__ __nv_bfloat16 g_qkv[(size_t)M_TOK * 768];
__device__ __nv_bfloat16 g_o  [(size_t)M_TOK * C_DIM];
__device__ float         g_x2 [(size_t)M_TOK * C_DIM];
__device__ __nv_bfloat16 g_h  [(size_t)M_TOK * C_DIM];
__device__ __nv_bfloat16 g_fc1[(size_t)M_TOK * 1024];
__device__ __nv_bfloat16 g_wqkvT[768 * 256];
__device__ __nv_bfloat16 g_wprojT[256 * 256];
__device__ __nv_bfloat16 g_wfc1T[1024 * 256];
__device__ __nv_bfloat16 g_wfc2T[256 * 1024];
__device__ float g_amask[64 * 8 * 8 * 512];     // frag-ordered bias+mask, 8 MB

// ---------------------------------------------------------------------------
__device__ __forceinline__ uint32_t smem_u32(const void* p) {
    uint32_t a;
    asm("{ .reg .u64 t; cvta.to.shared.u64 t, %1; cvt.u32.u64 %0, t; }" : "=r"(a) : "l"(p));
    return a;
}
__device__ __forceinline__ void ldsm4(uint32_t* r, uint32_t addr) {
    asm volatile("ldmatrix.sync.aligned.m8n8.x4.shared.b16 {%0,%1,%2,%3}, [%4];"
                 : "=r"(r[0]), "=r"(r[1]), "=r"(r[2]), "=r"(r[3]) : "r"(addr));
}
__device__ __forceinline__ void mma16816(float* c, const uint32_t* a, const uint32_t* b) {
    asm volatile(
        "mma.sync.aligned.m16n8k16.row.col.f32.bf16.bf16.f32 "
        "{%0,%1,%2,%3}, {%4,%5,%6,%7}, {%8,%9}, {%0,%1,%2,%3};"
        : "+f"(c[0]), "+f"(c[1]), "+f"(c[2]), "+f"(c[3])
        : "r"(a[0]), "r"(a[1]), "r"(a[2]), "r"(a[3]), "r"(b[0]), "r"(b[1]));
}
__device__ __forceinline__ uint32_t pack2(float a, float b) {
    __nv_bfloat162 h = __floats2bfloat162_rn(a, b);
    return *(uint32_t*)&h;
}
__device__ __forceinline__ float fexp(float x) {
    float z = fmaxf(x * 1.4426950408889634f, -126.0f);
    float t = z + 12582912.0f;
    int   i = __float_as_int(t) - 0x4B400000;
    float f = z - (t - 12582912.0f);
    float p = 0.00961804886f;
    p = fmaf(p, f, 0.05550410866f);
    p = fmaf(p, f, 0.24022650696f);
    p = fmaf(p, f, 0.69314718056f);
    p = fmaf(p, f, 1.0f);
    return __int_as_float(__float_as_int(p) + (i << 23));
}
#define CP16(dst, src) asm volatile("cp.async.cg.shared.global [%0], [%1], 16;" :: "r"(dst), "l"(src))
#define CP_COMMIT()    asm volatile("cp.async.commit_group;" ::: "memory")
#define CP_WAIT1()     asm volatile("cp.async.wait_group 1;" ::: "memory")
#define CP_WAIT2()     asm volatile("cp.async.wait_group 2;" ::: "memory")

// ---------------------------------------------------------------------------
__global__ void wconv_kernel(const float* __restrict__ in, __nv_bfloat16* __restrict__ out,
                             int K, int N)
{
    int id = blockIdx.x * 256 + threadIdx.x;
    if (id >= K * N) return;
    int n = id / K, k = id - n * K;
    out[id] = __float2bfloat16(in[(size_t)k * N + n]);
}

// frag-ordered combined mask: amask[wt][h][seg][lane][i]
// seg = am*2+half; row = am*16 + (lane>>2) + half*8; col = (i>>1)*8 + (lane&3)*2 + (i&1)
__global__ void amask_kernel(const float* __restrict__ rel_table,
                             const int* __restrict__ rel_idx,
                             const float* __restrict__ attn_mask,
                             float* __restrict__ out)
{
    int idx = blockIdx.x * 256 + threadIdx.x;
    if (idx >= 64 * 8 * 8 * 512) return;
    int i    = idx & 15;
    int lane = (idx >> 4) & 31;
    int seg  = (idx >> 9) & 7;
    int h    = (idx >> 12) & 7;
    int wt   = idx >> 15;
    int am = seg >> 1, half = seg & 1;
    int row = am * 16 + (lane >> 2) + half * 8;
    int col = (i >> 1) * 8 + (lane & 3) * 2 + (i & 1);
    float v = -3.402823466e38f;
    if (row < NSEQ && col < NSEQ && row != col)
        v = rel_table[rel_idx[row * NSEQ + col] * NHEADS + h]
          + attn_mask[wt * NSEQ * NSEQ + row * NSEQ + col];
    out[idx] = v;
}

// ---------------------------------------------------------------------------
// LayerNorm: warp-per-token. 8 tokens / block.
// ---------------------------------------------------------------------------
__global__ __launch_bounds__(256) void ln_kernel(
    const float* __restrict__ x,
    const float* __restrict__ gamma,
    const float* __restrict__ beta,
    __nv_bfloat16* __restrict__ out,
    int shifted)
{
    int wid = threadIdx.x >> 5, lane = threadIdx.x & 31;
    int t = blockIdx.x * 8 + wid;
    int src;
    if (shifted) {
        int wi  = t / NSEQ;
        int pos = t - wi * NSEQ;
        int b    = wi >> 6;
        int wrem = wi & 63;
        int hs = (wrem >> 3) * 7 + pos / 7;
        int ws = (wrem & 7) * 7 + pos % 7;
        int sh = hs + 3; if (sh >= 56) sh -= 56;
        int sw = ws + 3; if (sw >= 56) sw -= 56;
        src = b * 3136 + sh * 56 + sw;
    } else {
        src = t;
    }
    const float* row = x + (size_t)src * C_DIM + lane * 8;
    float4 v0 = *(const float4*)(row);
    float4 v1 = *(const float4*)(row + 4);
    float v[8] = {v0.x, v0.y, v0.z, v0.w, v1.x, v1.y, v1.z, v1.w};
    float s = 0.f, s2 = 0.f;
    #pragma unroll
    for (int i = 0; i < 8; i++) { s += v[i]; s2 += v[i] * v[i]; }
    #pragma unroll
    for (int off = 16; off; off >>= 1) {
        s  += __shfl_xor_sync(0xffffffffu, s,  off);
        s2 += __shfl_xor_sync(0xffffffffu, s2, off);
    }
    float mean = s * (1.f / 256.f);
    float var  = s2 * (1.f / 256.f) - mean * mean;
    float r = rsqrtf(var + 1e-6f);
    const float* g4 = gamma + lane * 8;
    const float* b4 = beta + lane * 8;
    uint32_t o4[4];
    #pragma unroll
    for (int i = 0; i < 4; i++) {
        float a0 = (v[2*i]   - mean) * r * g4[2*i]   + b4[2*i];
        float a1 = (v[2*i+1] - mean) * r * g4[2*i+1] + b4[2*i+1];
        o4[i] = pack2(a0, a1);
    }
    *(uint4*)(out + (size_t)t * C_DIM + lane * 8) = *(uint4*)o4;
}

// ---------------------------------------------------------------------------
// Shared epilogue: per 64x64 warp tile.
// ---------------------------------------------------------------------------
template<int EPI>
__device__ __forceinline__ void gemm_epilogue(
    float acc[4][8][4], const float* sbias, const float* residual,
    void* outv, int Nc, int bm, int bn, int wm, int wn, int lane)
{
    const int n0 = bn + wn * 64 + (lane & 3) * 2;
    const int m0 = bm + wm * 64 + (lane >> 2);

    #pragma unroll
    for (int am = 0; am < 4; am++) {
        int mA = m0 + am * 16;
        int dstA = mA, dstB = mA + 8;
        if (EPI == 3) {
            #pragma unroll
            for (int h = 0; h < 2; h++) {
                int m = mA + h * 8;
                int wi  = m / NSEQ;
                int pos = m - wi * NSEQ;
                int b    = wi >> 6;
                int wrem = wi & 63;
                int hs = (wrem >> 3) * 7 + pos / 7;
                int ws = (wrem & 7) * 7 + pos % 7;
                int dh = hs + 3; if (dh >= 56) dh -= 56;
                int dw = ws + 3; if (dw >= 56) dw -= 56;
                int d = b * 3136 + dh * 56 + dw;
                if (h == 0) dstA = d; else dstB = d;
            }
        }
        #pragma unroll
        for (int nn = 0; nn < 8; nn++) {
            int col = n0 + nn * 8;
            float b0 = sbias[col - bn], b1 = sbias[col - bn + 1];
            float c0 = acc[am][nn][0] + b0, c1 = acc[am][nn][1] + b1;
            float c2 = acc[am][nn][2] + b0, c3 = acc[am][nn][3] + b1;
            if (EPI == 1) {
                c0 = c0 * 0.5f * (1.f + erff(c0 * 0.70710678118654752f));
                c1 = c1 * 0.5f * (1.f + erff(c1 * 0.70710678118654752f));
                c2 = c2 * 0.5f * (1.f + erff(c2 * 0.70710678118654752f));
                c3 = c3 * 0.5f * (1.f + erff(c3 * 0.70710678118654752f));
            }
            if (EPI == 0 || EPI == 1) {
                __nv_bfloat16* out = (__nv_bfloat16*)outv;
                *(uint32_t*)(out + (size_t)mA * Nc + col)       = pack2(c0, c1);
                *(uint32_t*)(out + (size_t)(mA + 8) * Nc + col) = pack2(c2, c3);
            } else {
                float* out = (float*)outv;
                float2 r0 = *(const float2*)(residual + (size_t)dstA * Nc + col);
                float2 r1 = *(const float2*)(residual + (size_t)dstB * Nc + col);
                *(float2*)(out + (size_t)dstA * Nc + col) = make_float2(c0 + r0.x, c1 + r0.y);
                *(float2*)(out + (size_t)dstB * Nc + col) = make_float2(c2 + r1.x, c3 + r1.y);
            }
        }
    }
}

// ---------------------------------------------------------------------------
// Persistent B-panel GEMM (K=256): B panel resident, A 3-stage stream.
// ---------------------------------------------------------------------------
#define KP 40
#define BCH (128 * KP * 2)            // 10240 B per chunk-tile
#define PB_SMEM (8 * BCH + 3 * BCH)   // 112640

template<int EPI>
__global__ __launch_bounds__(128) void gemm_pb(
    const __nv_bfloat16* __restrict__ A,
    const __nv_bfloat16* __restrict__ Bt,
    const float* __restrict__ bias,
    const float* __restrict__ residual,
    void* __restrict__ outv,
    int Nc)
{
    extern __shared__ __align__(16) uint8_t smem[];
    __shared__ float sbias[128];

    const int tid = threadIdx.x;
    const int lane = tid & 31, wid = tid >> 5;
    const int wm = wid & 1;
    const int wn = wid >> 1;
    const int bn = blockIdx.x * 128;
    const int GY = gridDim.y;

    sbias[tid] = bias[bn + tid];

    const uint32_t sBase = smem_u32(smem);
    const uint32_t aBase = sBase + 8 * BCH;

    const int lr = tid >> 2;
    const int lc = (tid & 3) * 8;

    // B panel
    {
        const __nv_bfloat16* Bb = Bt + (size_t)bn * 256;
        #pragma unroll
        for (int ch = 0; ch < 8; ch++)
            #pragma unroll
            for (int j = 0; j < 4; j++) {
                int r = lr + j * 32;
                CP16(sBase + ch * BCH + (uint32_t)(r * KP + lc) * 2,
                     Bb + (size_t)r * 256 + ch * 32 + lc);
            }
        CP_COMMIT();
    }

    const int nTiles = (NMT - blockIdx.y + GY - 1) / GY;
    const int T = nTiles * 8;

    // A prologue: chunks 0,1 -> stages 0,1
    #pragma unroll
    for (int s = 0; s < 2; s++) {
        if (s < T) {
            int mt = blockIdx.y + (s >> 3) * GY;
            const __nv_bfloat16* Ab = A + (size_t)mt * 128 * 256 + (s & 7) * 32;
            #pragma unroll
            for (int j = 0; j < 4; j++) {
                int r = lr + j * 32;
                CP16(aBase + s * BCH + (uint32_t)(r * KP + lc) * 2, Ab + (size_t)r * 256 + lc);
            }
        }
        CP_COMMIT();
    }

    const uint32_t aRowB = (uint32_t)(wm * 64 + (lane & 15));
    const uint32_t aKH   = (lane & 16) ? 8u : 0u;
    const uint32_t bRowB = (uint32_t)(wn * 64 + (lane & 7) + ((lane & 16) ? 8 : 0));
    const uint32_t bKH   = (lane & 8) ? 8u : 0u;

    float acc[4][8][4];
    #pragma unroll
    for (int i = 0; i < 4; i++)
        #pragma unroll
        for (int j = 0; j < 8; j++)
            #pragma unroll
            for (int t = 0; t < 4; t++) acc[i][j][t] = 0.f;

    for (int g = 0; g < T; g++) {
        int kc = g & 7;
        CP_WAIT1();      // B + A-chunk g done; A-chunk g+1 may be in flight
        __syncthreads();

        if (g + 2 < T) {
            int g2 = g + 2;
            int mt2 = blockIdx.y + (g2 >> 3) * GY;
            const __nv_bfloat16* Ab = A + (size_t)mt2 * 128 * 256 + (g2 & 7) * 32;
            uint32_t st = aBase + (uint32_t)(g2 % 3) * BCH;
            #pragma unroll
            for (int j = 0; j < 4; j++) {
                int r = lr + j * 32;
                CP16(st + (uint32_t)(r * KP + lc) * 2, Ab + (size_t)r * 256 + lc);
            }
        }
        CP_COMMIT();

        const uint32_t aS = aBase + (uint32_t)(g % 3) * BCH;
        const uint32_t bS = sBase + (uint32_t)kc * BCH;
        #pragma unroll
        for (int ks = 0; ks < 2; ks++) {
            uint32_t af[4][4], bf[4][4];
            #pragma unroll
            for (int am = 0; am < 4; am++)
                ldsm4(af[am], aS + ((aRowB + am * 16) * KP + ks * 16 + aKH) * 2);
            #pragma unroll
            for (int gi = 0; gi < 4; gi++)
                ldsm4(bf[gi], bS + ((bRowB + gi * 16) * KP + ks * 16 + bKH) * 2);
            #pragma unroll
            for (int am = 0; am < 4; am++)
                #pragma unroll
                for (int nn = 0; nn < 8; nn++)
                    mma16816(acc[am][nn], af[am], &bf[nn >> 1][(nn & 1) * 2]);
        }

        if (kc == 7) {
            int bm = (blockIdx.y + (g >> 3) * GY) * 128;
            gemm_epilogue<EPI>(acc, sbias, residual, outv, Nc, bm, bn, wm, wn, lane);
            #pragma unroll
            for (int i = 0; i < 4; i++)
                #pragma unroll
                for (int j = 0; j < 8; j++)
                    #pragma unroll
                    for (int t = 0; t < 4; t++) acc[i][j][t] = 0.f;
        }
    }
}

// ---------------------------------------------------------------------------
// Streaming GEMM for fc2 (K=1024): R8 config.
// ---------------------------------------------------------------------------
#define STAGE_B (2 * BCH)
#define B_OFF   BCH
#define ST_SMEM (4 * STAGE_B)

template<int EPI>
__global__ __launch_bounds__(128) void gemm_st(
    const __nv_bfloat16* __restrict__ A,
    const __nv_bfloat16* __restrict__ Bt,
    const float* __restrict__ bias,
    const float* __restrict__ residual,
    void* __restrict__ outv,
    int K, int Nc)
{
    extern __shared__ __align__(16) uint8_t smem[];
    __shared__ float sbias[128];

    const int tid = threadIdx.x;
    const int lane = tid & 31, wid = tid >> 5;
    const int wm = wid & 1;
    const int wn = wid >> 1;
    const int bn = blockIdx.x * 128, bm = blockIdx.y * 128;

    sbias[tid] = bias[bn + tid];

    const uint32_t sBase = smem_u32(smem);

    const int ldr0 = tid >> 2;
    const int ldc  = (tid & 3) * 8;

    const uint32_t aRowB = (uint32_t)(wm * 64 + (lane & 15));
    const uint32_t aKH   = (lane & 16) ? 8u : 0u;
    const uint32_t bRowB = (uint32_t)(wn * 64 + (lane & 7) + ((lane & 16) ? 8 : 0));
    const uint32_t bKH   = (lane & 8) ? 8u : 0u;

    float acc[4][8][4];
    #pragma unroll
    for (int i = 0; i < 4; i++)
        #pragma unroll
        for (int j = 0; j < 8; j++)
            #pragma unroll
            for (int t = 0; t < 4; t++) acc[i][j][t] = 0.f;

    const int nk = K >> 5;

    #pragma unroll
    for (int s = 0; s < 3; s++) {
        uint32_t st = sBase + s * STAGE_B;
        const __nv_bfloat16* Ab = A + (size_t)bm * K + s * 32;
        const __nv_bfloat16* Bb = Bt + (size_t)bn * K + s * 32;
        #pragma unroll
        for (int j = 0; j < 4; j++) {
            int r = ldr0 + j * 32;
            CP16(st + (uint32_t)(r * KP + ldc) * 2,         Ab + (size_t)r * K + ldc);
            CP16(st + B_OFF + (uint32_t)(r * KP + ldc) * 2, Bb + (size_t)r * K + ldc);
        }
        CP_COMMIT();
    }

    for (int kc = 0; kc < nk; kc++) {
        CP_WAIT2();
        __syncthreads();

        if (kc + 3 < nk) {
            uint32_t st = sBase + ((kc + 3) & 3) * STAGE_B;
            const __nv_bfloat16* Ab = A + (size_t)bm * K + (kc + 3) * 32;
            const __nv_bfloat16* Bb = Bt + (size_t)bn * K + (kc + 3) * 32;
            #pragma unroll
            for (int j = 0; j < 4; j++) {
                int r = ldr0 + j * 32;
                CP16(st + (uint32_t)(r * KP + ldc) * 2,         Ab + (size_t)r * K + ldc);
                CP16(st + B_OFF + (uint32_t)(r * KP + ldc) * 2, Bb + (size_t)r * K + ldc);
            }
        }
        CP_COMMIT();

        const uint32_t aS = sBase + (kc & 3) * STAGE_B;
        const uint32_t bS = aS + B_OFF;
        #pragma unroll
        for (int ks = 0; ks < 2; ks++) {
            uint32_t af[4][4], bf[4][4];
            #pragma unroll
            for (int am = 0; am < 4; am++)
                ldsm4(af[am], aS + ((aRowB + am * 16) * KP + ks * 16 + aKH) * 2);
            #pragma unroll
            for (int g = 0; g < 4; g++)
                ldsm4(bf[g], bS + ((bRowB + g * 16) * KP + ks * 16 + bKH) * 2);
            #pragma unroll
            for (int am = 0; am < 4; am++)
                #pragma unroll
                for (int nn = 0; nn < 8; nn++)
                    mma16816(acc[am][nn], af[am], &bf[nn >> 1][(nn & 1) * 2]);
        }
    }

    gemm_epilogue<EPI>(acc, sbias, residual, outv, Nc, bm, bn, wm, wn, lane);
}

// ---------------------------------------------------------------------------
// Fused-window attention with frag-ordered mask table.
// ---------------------------------------------------------------------------
#define AQ_STR 40
#define AV_STR 72
#define ATTN_QS   0
#define ATTN_KB   (8 * 64 * AQ_STR)
#define ATTN_VT   (ATTN_KB + 8 * 64 * AQ_STR)
#define ATTN_SMEM ((ATTN_VT + 8 * 32 * AV_STR) * 2)

__global__ __launch_bounds__(256) void attn_kernel(
    const __nv_bfloat16* __restrict__ qkv,
    const float* __restrict__ amask,
    const float* __restrict__ temperature,
    __nv_bfloat16* __restrict__ o)
{
    extern __shared__ __align__(16) __nv_bfloat16 sm[];
    const int wi = blockIdx.x;
    const int tid = threadIdx.x;
    const int h = tid >> 5, lane = tid & 31;

    const float scale = expf(temperature[0]);
    const __nv_bfloat16* base = qkv + (size_t)wi * NSEQ * 768;

    {
        uint4 z = make_uint4(0, 0, 0, 0);
        uint4* v = (uint4*)(sm + ATTN_VT);
        for (int i = tid; i < 8 * 32 * AV_STR / 8; i += 256) v[i] = z;
    }
    for (int idx = tid; idx < NSEQ * 96; idx += 256) {
        int r = idx / 96, u = idx - r * 96;
        int c0 = u * 8;
        uint4 val = *(const uint4*)(base + (size_t)r * 768 + c0);
        int ten = c0 >> 8;
        int within = c0 & 255;
        int hh = within >> 5, d = within & 31;
        if (ten == 0) {
            *(uint4*)(sm + ATTN_QS + hh * 64 * AQ_STR + r * AQ_STR + d) = val;
        } else if (ten == 1) {
            *(uint4*)(sm + ATTN_KB + hh * 64 * AQ_STR + r * AQ_STR + d) = val;
        } else {
            const __nv_bfloat16* e = (const __nv_bfloat16*)&val;
            __nv_bfloat16* vt = sm + ATTN_VT + hh * 32 * AV_STR;
            #pragma unroll
            for (int j = 0; j < 8; j++) vt[(d + j) * AV_STR + r] = e[j];
        }
    }
    __syncthreads();

    const uint32_t qB = smem_u32(sm + ATTN_QS + h * 64 * AQ_STR);
    const uint32_t kB = smem_u32(sm + ATTN_KB + h * 64 * AQ_STR);
    const uint32_t vB = smem_u32(sm + ATTN_VT + h * 32 * AV_STR);

    const uint32_t aRow = (uint32_t)(lane & 15);
    const uint32_t aKH  = (lane & 16) ? 8u : 0u;
    const uint32_t bRow = (uint32_t)((lane & 7) + ((lane & 16) ? 8 : 0));
    const uint32_t bKH  = (lane & 8) ? 8u : 0u;

    float acc[4][8][4];
    #pragma unroll
    for (int i = 0; i < 4; i++)
        #pragma unroll
        for (int j = 0; j < 8; j++)
            #pragma unroll
            for (int t = 0; t < 4; t++) acc[i][j][t] = 0.f;

    #pragma unroll
    for (int ks = 0; ks < 2; ks++) {
        uint32_t af[4][4], bf[4][4];
        #pragma unroll
        for (int am = 0; am < 4; am++)
            ldsm4(af[am], qB + ((aRow + am * 16) * AQ_STR + ks * 16 + aKH) * 2);
        #pragma unroll
        for (int g = 0; g < 4; g++)
            ldsm4(bf[g], kB + ((bRow + g * 16) * AQ_STR + ks * 16 + bKH) * 2);
        #pragma unroll
        for (int am = 0; am < 4; am++)
            #pragma unroll
            for (int nn = 0; nn < 8; nn++)
                mma16816(acc[am][nn], af[am], &bf[nn >> 1][(nn & 1) * 2]);
    }

    // frag softmax with coalesced mask-table loads
    const float* tb = amask + (((size_t)(wi & 63) * 8 + h) << 12);
    uint32_t afP[4][4][4];

    #pragma unroll
    for (int am = 0; am < 4; am++) {
        #pragma unroll
        for (int half = 0; half < 2; half++) {
            const float4* tseg = (const float4*)(tb + (((am << 1) + half) << 9) + (lane << 4));
            float4 t0 = tseg[0], t1 = tseg[1], t2 = tseg[2], t3 = tseg[3];
            float tv[16] = {t0.x, t0.y, t0.z, t0.w, t1.x, t1.y, t1.z, t1.w,
                            t2.x, t2.y, t2.z, t2.w, t3.x, t3.y, t3.z, t3.w};
            float e[16];
            float mx = -3.402823466e38f;
            #pragma unroll
            for (int nt = 0; nt < 8; nt++) {
                #pragma unroll
                for (int j = 0; j < 2; j++) {
                    float s = fmaf(acc[am][nt][half * 2 + j], scale, tv[nt * 2 + j]);
                    e[nt * 2 + j] = s;
                    mx = fmaxf(mx, s);
                }
            }
            mx = fmaxf(mx, __shfl_xor_sync(0xffffffffu, mx, 1));
            mx = fmaxf(mx, __shfl_xor_sync(0xffffffffu, mx, 2));
            float sum = 0.f;
            #pragma unroll
            for (int i = 0; i < 16; i++) { e[i] = fexp(e[i] - mx); sum += e[i]; }
            sum += __shfl_xor_sync(0xffffffffu, sum, 1);
            sum += __shfl_xor_sync(0xffffffffu, sum, 2);
            float inv = 1.f / sum;
            #pragma unroll
            for (int ks = 0; ks < 4; ks++) {
                uint32_t lo = pack2(e[4 * ks] * inv,     e[4 * ks + 1] * inv);
                uint32_t hi = pack2(e[4 * ks + 2] * inv, e[4 * ks + 3] * inv);
                afP[am][ks][half]     = lo;
                afP[am][ks][2 + half] = hi;
            }
        }
    }

    float accP[4][4][4];
    #pragma unroll
    for (int i = 0; i < 4; i++)
        #pragma unroll
        for (int j = 0; j < 4; j++)
            #pragma unroll
            for (int t = 0; t < 4; t++) accP[i][j][t] = 0.f;

    #pragma unroll
    for (int ks = 0; ks < 4; ks++) {
        uint32_t bf[2][4];
        #pragma unroll
        for (int g = 0; g < 2; g++)
            ldsm4(bf[g], vB + ((bRow + g * 16) * AV_STR + ks * 16 + bKH) * 2);
        #pragma unroll
        for (int am = 0; am < 4; am++)
            #pragma unroll
            for (int nn = 0; nn < 4; nn++)
                mma16816(accP[am][nn], afP[am][ks], &bf[nn >> 1][(nn & 1) * 2]);
    }

    #pragma unroll
    for (int am = 0; am < 4; am++) {
        int n = am * 16 + (lane >> 2);
        int d0 = (lane & 3) * 2;
        #pragma unroll
        for (int nn = 0; nn < 4; nn++) {
            int d = d0 + nn * 8;
            if (n < NSEQ)
                *(uint32_t*)(o + (size_t)(wi * NSEQ + n) * C_DIM + h * HDIM + d)
                    = pack2(accP[am][nn][0], accP[am][nn][1]);
            if (n + 8 < NSEQ)
                *(uint32_t*)(o + (size_t)(wi * NSEQ + n + 8) * C_DIM + h * HDIM + d)
                    = pack2(accP[am][nn][2], accP[am][nn][3]);
        }
    }
}

// ---------------------------------------------------------------------------
extern "C" void kernel_launch(void* const* d_in, const int* in_sizes, int n_in,
                              void* d_out, int out_size)
{
    const float* x        = (const float*)d_in[0];
    const float* attn_msk = (const float*)d_in[1];
    const float* norm1_g  = (const float*)d_in[2];
    const float* norm1_b  = (const float*)d_in[3];
    const float* qkv_w    = (const float*)d_in[4];
    const float* qkv_b    = (const float*)d_in[5];
    const float* temp     = (const float*)d_in[6];
    const float* rel_tab  = (const float*)d_in[7];
    const float* proj_w   = (const float*)d_in[8];
    const float* proj_b   = (const float*)d_in[9];
    const float* norm2_g  = (const float*)d_in[10];
    const float* norm2_b  = (const float*)d_in[11];
    const float* fc1_w    = (const float*)d_in[12];
    const float* fc1_b    = (const float*)d_in[13];
    const float* fc2_w    = (const float*)d_in[14];
    const float* fc2_b    = (const float*)d_in[15];
    const int*   rel_idx  = (const int*)d_in[16];
    float* out = (float*)d_out;

    __nv_bfloat16 *zw, *qkv, *o, *hbuf, *fc1, *wqkvT, *wprojT, *wfc1T, *wfc2T;
    float *x2, *amask;
    cudaGetSymbolAddress((void**)&zw,    g_zw);
    cudaGetSymbolAddress((void**)&qkv,   g_qkv);
    cudaGetSymbolAddress((void**)&o,     g_o);
    cudaGetSymbolAddress((void**)&x2,    g_x2);
    cudaGetSymbolAddress((void**)&hbuf,  g_h);
    cudaGetSymbolAddress((void**)&fc1,   g_fc1);
    cudaGetSymbolAddress((void**)&wqkvT, g_wqkvT);
    cudaGetSymbolAddress((void**)&wprojT,g_wprojT);
    cudaGetSymbolAddress((void**)&wfc1T, g_wfc1T);
    cudaGetSymbolAddress((void**)&wfc2T, g_wfc2T);
    cudaGetSymbolAddress((void**)&amask, g_amask);

    static bool attr_done = false;
    if (!attr_done) {
        cudaFuncSetAttribute(gemm_pb<0>, cudaFuncAttributeMaxDynamicSharedMemorySize, PB_SMEM);
        cudaFuncSetAttribute(gemm_pb<1>, cudaFuncAttributeMaxDynamicSharedMemorySize, PB_SMEM);
        cudaFuncSetAttribute(gemm_pb<3>, cudaFuncAttributeMaxDynamicSharedMemorySize, PB_SMEM);
        cudaFuncSetAttribute(gemm_st<2>, cudaFuncAttributeMaxDynamicSharedMemorySize, ST_SMEM);
        cudaFuncSetAttribute(attn_kernel, cudaFuncAttributeMaxDynamicSharedMemorySize, ATTN_SMEM);
        attr_done = true;
    }

    wconv_kernel<<<(256 * 768 + 255) / 256, 256>>>(qkv_w, wqkvT, 256, 768);          // 0
    ln_kernel<<<M_TOK / 8, 256>>>(x, norm1_g, norm1_b, zw, 1);                        // 1
    amask_kernel<<<(64 * 8 * 8 * 512) / 256, 256>>>(rel_tab, rel_idx, attn_msk, amask);// 2
    gemm_pb<0><<<dim3(6, 48), 128, PB_SMEM>>>(zw, wqkvT, qkv_b, nullptr, qkv, 768);   // 3
    wconv_kernel<<<(256 * 256 + 255) / 256, 256>>>(proj_w, wprojT, 256, 256);         // 4
    wconv_kernel<<<(256 * 1024 + 255) / 256, 256>>>(fc1_w, wfc1T, 256, 1024);         // 5
    wconv_kernel<<<(1024 * 256 + 255) / 256, 256>>>(fc2_w, wfc2T, 1024, 256);         // 6
    attn_kernel<<<NWIN, 256, ATTN_SMEM>>>(qkv, amask, temp, o);                       // 7
    gemm_pb<3><<<dim3(2, 148), 128, PB_SMEM>>>(o, wprojT, proj_b, x, x2, 256);        // 8
    ln_kernel<<<M_TOK / 8, 256>>>(x2, norm2_g, norm2_b, hbuf, 0);                     // 9
    gemm_pb<1><<<dim3(8, 37), 128, PB_SMEM>>>(hbuf, wfc1T, fc1_b, nullptr, fc1, 1024);// 10
    gemm_st<2><<<dim3(2, NMT), 128, ST_SMEM>>>(fc1, wfc2T, fc2_b, x2, out, 1024, 256);// 11
}

// round 15
// speedup vs baseline: 1.1688x; 1.0044x over previous
#include <cuda_runtime.h>
#include <cuda_bf16.h>
#include <math.h>
#include <stdint.h>

// ---------------------------------------------------------------------------
// SwinTransformerBlock on GB300: persistent B-panel bf16 GEMMs + fused attn
// ---------------------------------------------------------------------------

#define M_TOK   100352
#define C_DIM   256
#define NHEADS  8
#define HDIM    32
#define NWIN    2048
#define NSEQ    49
#define NMT     784

__device__ __nv_bfloat16 g_zw [(size_t)M_TOK * C_DIM];
__device__ __nv_bfloat16 g_qkv[(size_t)M_TOK * 768];
__device__ __nv_bfloat16 g_o  [(size_t)M_TOK * C_DIM];
__device__ float         g_x2 [(size_t)M_TOK * C_DIM];
__device__ __nv_bfloat16 g_h  [(size_t)M_TOK * C_DIM];
__device__ __nv_bfloat16 g_fc1[(size_t)M_TOK * 1024];
__device__ __nv_bfloat16 g_wqkvT[768 * 256];
__device__ __nv_bfloat16 g_wprojT[256 * 256];
__device__ __nv_bfloat16 g_wfc1T[1024 * 256];
__device__ __nv_bfloat16 g_wfc2T[256 * 1024];
__device__ float g_amask[64 * 8 * 8 * 512];

// ---------------------------------------------------------------------------
__device__ __forceinline__ uint32_t smem_u32(const void* p) {
    uint32_t a;
    asm("{ .reg .u64 t; cvta.to.shared.u64 t, %1; cvt.u32.u64 %0, t; }" : "=r"(a) : "l"(p));
    return a;
}
__device__ __forceinline__ void ldsm4(uint32_t* r, uint32_t addr) {
    asm volatile("ldmatrix.sync.aligned.m8n8.x4.shared.b16 {%0,%1,%2,%3}, [%4];"
                 : "=r"(r[0]), "=r"(r[1]), "=r"(r[2]), "=r"(r[3]) : "r"(addr));
}
__device__ __forceinline__ void mma16816(float* c, const uint32_t* a, const uint32_t* b) {
    asm volatile(
        "mma.sync.aligned.m16n8k16.row.col.f32.bf16.bf16.f32 "
        "{%0,%1,%2,%3}, {%4,%5,%6,%7}, {%8,%9}, {%0,%1,%2,%3};"
        : "+f"(c[0]), "+f"(c[1]), "+f"(c[2]), "+f"(c[3])
        : "r"(a[0]), "r"(a[1]), "r"(a[2]), "r"(a[3]), "r"(b[0]), "r"(b[1]));
}
__device__ __forceinline__ uint32_t pack2(float a, float b) {
    __nv_bfloat162 h = __floats2bfloat162_rn(a, b);
    return *(uint32_t*)&h;
}
__device__ __forceinline__ float fexp(float x) {
    float z = fmaxf(x * 1.4426950408889634f, -126.0f);
    float t = z + 12582912.0f;
    int   i = __float_as_int(t) - 0x4B400000;
    float f = z - (t - 12582912.0f);
    float p = 0.00961804886f;
    p = fmaf(p, f, 0.05550410866f);
    p = fmaf(p, f, 0.24022650696f);
    p = fmaf(p, f, 0.69314718056f);
    p = fmaf(p, f, 1.0f);
    return __int_as_float(__float_as_int(p) + (i << 23));
}
#define CP16(dst, src) asm volatile("cp.async.cg.shared.global [%0], [%1], 16;" :: "r"(dst), "l"(src))
#define CP_COMMIT()    asm volatile("cp.async.commit_group;" ::: "memory")
#define CP_WAIT1()     asm volatile("cp.async.wait_group 1;" ::: "memory")
#define CP_WAIT2()     asm volatile("cp.async.wait_group 2;" ::: "memory")

// ---------------------------------------------------------------------------
// prep: all 4 weight transposes + amask table in one launch (range split).
// ---------------------------------------------------------------------------
__device__ __forceinline__ void wconv_elem(int id, const float* in,
                                           __nv_bfloat16* out, int K, int N)
{
    int n = id / K, k = id - n * K;
    out[id] = __float2bfloat16(in[(size_t)k * N + n]);
}

#define PR0 (256 * 768)
#define PR1 (PR0 + 256 * 256)
#define PR2 (PR1 + 256 * 1024)
#define PR3 (PR2 + 1024 * 256)
#define PR4 (PR3 + 64 * 8 * 8 * 512)

__global__ void prep_kernel(
    const float* __restrict__ qkv_w, const float* __restrict__ proj_w,
    const float* __restrict__ fc1_w, const float* __restrict__ fc2_w,
    __nv_bfloat16* __restrict__ wqkvT, __nv_bfloat16* __restrict__ wprojT,
    __nv_bfloat16* __restrict__ wfc1T, __nv_bfloat16* __restrict__ wfc2T,
    const float* __restrict__ rel_table, const int* __restrict__ rel_idx,
    const float* __restrict__ attn_mask, float* __restrict__ amask)
{
    int gid = blockIdx.x * 256 + threadIdx.x;
    if (gid < PR0) {
        wconv_elem(gid, qkv_w, wqkvT, 256, 768);
    } else if (gid < PR1) {
        wconv_elem(gid - PR0, proj_w, wprojT, 256, 256);
    } else if (gid < PR2) {
        wconv_elem(gid - PR1, fc1_w, wfc1T, 256, 1024);
    } else if (gid < PR3) {
        wconv_elem(gid - PR2, fc2_w, wfc2T, 1024, 256);
    } else if (gid < PR4) {
        int idx = gid - PR3;
        int i    = idx & 15;
        int lane = (idx >> 4) & 31;
        int seg  = (idx >> 9) & 7;
        int h    = (idx >> 12) & 7;
        int wt   = idx >> 15;
        int am = seg >> 1, half = seg & 1;
        int row = am * 16 + (lane >> 2) + half * 8;
        int col = (i >> 1) * 8 + (lane & 3) * 2 + (i & 1);
        float v = -3.402823466e38f;
        if (row < NSEQ && col < NSEQ && row != col)
            v = rel_table[rel_idx[row * NSEQ + col] * NHEADS + h]
              + attn_mask[wt * NSEQ * NSEQ + row * NSEQ + col];
        amask[idx] = v;
    }
}

// ---------------------------------------------------------------------------
// LayerNorm: warp-per-token. 8 tokens / block.
// ---------------------------------------------------------------------------
__global__ __launch_bounds__(256) void ln_kernel(
    const float* __restrict__ x,
    const float* __restrict__ gamma,
    const float* __restrict__ beta,
    __nv_bfloat16* __restrict__ out,
    int shifted)
{
    int wid = threadIdx.x >> 5, lane = threadIdx.x & 31;
    int t = blockIdx.x * 8 + wid;
    int src;
    if (shifted) {
        int wi  = t / NSEQ;
        int pos = t - wi * NSEQ;
        int b    = wi >> 6;
        int wrem = wi & 63;
        int hs = (wrem >> 3) * 7 + pos / 7;
        int ws = (wrem & 7) * 7 + pos % 7;
        int sh = hs + 3; if (sh >= 56) sh -= 56;
        int sw = ws + 3; if (sw >= 56) sw -= 56;
        src = b * 3136 + sh * 56 + sw;
    } else {
        src = t;
    }
    const float* row = x + (size_t)src * C_DIM + lane * 8;
    float4 v0 = *(const float4*)(row);
    float4 v1 = *(const float4*)(row + 4);
    float v[8] = {v0.x, v0.y, v0.z, v0.w, v1.x, v1.y, v1.z, v1.w};
    float s = 0.f, s2 = 0.f;
    #pragma unroll
    for (int i = 0; i < 8; i++) { s += v[i]; s2 += v[i] * v[i]; }
    #pragma unroll
    for (int off = 16; off; off >>= 1) {
        s  += __shfl_xor_sync(0xffffffffu, s,  off);
        s2 += __shfl_xor_sync(0xffffffffu, s2, off);
    }
    float mean = s * (1.f / 256.f);
    float var  = s2 * (1.f / 256.f) - mean * mean;
    float r = rsqrtf(var + 1e-6f);
    const float* g4 = gamma + lane * 8;
    const float* b4 = beta + lane * 8;
    uint32_t o4[4];
    #pragma unroll
    for (int i = 0; i < 4; i++) {
        float a0 = (v[2*i]   - mean) * r * g4[2*i]   + b4[2*i];
        float a1 = (v[2*i+1] - mean) * r * g4[2*i+1] + b4[2*i+1];
        o4[i] = pack2(a0, a1);
    }
    *(uint4*)(out + (size_t)t * C_DIM + lane * 8) = *(uint4*)o4;
}

// ---------------------------------------------------------------------------
// Shared GEMM epilogue.
// ---------------------------------------------------------------------------
template<int EPI>
__device__ __forceinline__ void gemm_epilogue(
    float acc[4][8][4], const float* sbias, const float* residual,
    void* outv, int Nc, int bm, int bn, int wm, int wn, int lane)
{
    const int n0 = bn + wn * 64 + (lane & 3) * 2;
    const int m0 = bm + wm * 64 + (lane >> 2);

    #pragma unroll
    for (int am = 0; am < 4; am++) {
        int mA = m0 + am * 16;
        int dstA = mA, dstB = mA + 8;
        if (EPI == 3) {
            #pragma unroll
            for (int h = 0; h < 2; h++) {
                int m = mA + h * 8;
                int wi  = m / NSEQ;
                int pos = m - wi * NSEQ;
                int b    = wi >> 6;
                int wrem = wi & 63;
                int hs = (wrem >> 3) * 7 + pos / 7;
                int ws = (wrem & 7) * 7 + pos % 7;
                int dh = hs + 3; if (dh >= 56) dh -= 56;
                int dw = ws + 3; if (dw >= 56) dw -= 56;
                int d = b * 3136 + dh * 56 + dw;
                if (h == 0) dstA = d; else dstB = d;
            }
        }
        #pragma unroll
        for (int nn = 0; nn < 8; nn++) {
            int col = n0 + nn * 8;
            float b0 = sbias[col - bn], b1 = sbias[col - bn + 1];
            float c0 = acc[am][nn][0] + b0, c1 = acc[am][nn][1] + b1;
            float c2 = acc[am][nn][2] + b0, c3 = acc[am][nn][3] + b1;
            if (EPI == 1) {
                c0 = c0 * 0.5f * (1.f + erff(c0 * 0.70710678118654752f));
                c1 = c1 * 0.5f * (1.f + erff(c1 * 0.70710678118654752f));
                c2 = c2 * 0.5f * (1.f + erff(c2 * 0.70710678118654752f));
                c3 = c3 * 0.5f * (1.f + erff(c3 * 0.70710678118654752f));
            }
            if (EPI == 0 || EPI == 1) {
                __nv_bfloat16* out = (__nv_bfloat16*)outv;
                *(uint32_t*)(out + (size_t)mA * Nc + col)       = pack2(c0, c1);
                *(uint32_t*)(out + (size_t)(mA + 8) * Nc + col) = pack2(c2, c3);
            } else {
                float* out = (float*)outv;
                float2 r0 = *(const float2*)(residual + (size_t)dstA * Nc + col);
                float2 r1 = *(const float2*)(residual + (size_t)dstB * Nc + col);
                *(float2*)(out + (size_t)dstA * Nc + col) = make_float2(c0 + r0.x, c1 + r0.y);
                *(float2*)(out + (size_t)dstB * Nc + col) = make_float2(c2 + r1.x, c3 + r1.y);
            }
        }
    }
}

// ---------------------------------------------------------------------------
// Persistent B-panel GEMM (K=256): B panel resident, A 3-stage stream.
// ---------------------------------------------------------------------------
#define KP 40
#define BCH (128 * KP * 2)
#define PB_SMEM (8 * BCH + 3 * BCH)

template<int EPI>
__global__ __launch_bounds__(128) void gemm_pb(
    const __nv_bfloat16* __restrict__ A,
    const __nv_bfloat16* __restrict__ Bt,
    const float* __restrict__ bias,
    const float* __restrict__ residual,
    void* __restrict__ outv,
    int Nc)
{
    extern __shared__ __align__(16) uint8_t smem[];
    __shared__ float sbias[128];

    const int tid = threadIdx.x;
    const int lane = tid & 31, wid = tid >> 5;
    const int wm = wid & 1;
    const int wn = wid >> 1;
    const int bn = blockIdx.x * 128;
    const int GY = gridDim.y;

    sbias[tid] = bias[bn + tid];

    const uint32_t sBase = smem_u32(smem);
    const uint32_t aBase = sBase + 8 * BCH;

    const int lr = tid >> 2;
    const int lc = (tid & 3) * 8;

    {
        const __nv_bfloat16* Bb = Bt + (size_t)bn * 256;
        #pragma unroll
        for (int ch = 0; ch < 8; ch++)
            #pragma unroll
            for (int j = 0; j < 4; j++) {
                int r = lr + j * 32;
                CP16(sBase + ch * BCH + (uint32_t)(r * KP + lc) * 2,
                     Bb + (size_t)r * 256 + ch * 32 + lc);
            }
        CP_COMMIT();
    }

    const int nTiles = (NMT - blockIdx.y + GY - 1) / GY;
    const int T = nTiles * 8;

    #pragma unroll
    for (int s = 0; s < 2; s++) {
        if (s < T) {
            int mt = blockIdx.y + (s >> 3) * GY;
            const __nv_bfloat16* Ab = A + (size_t)mt * 128 * 256 + (s & 7) * 32;
            #pragma unroll
            for (int j = 0; j < 4; j++) {
                int r = lr + j * 32;
                CP16(aBase + s * BCH + (uint32_t)(r * KP + lc) * 2, Ab + (size_t)r * 256 + lc);
            }
        }
        CP_COMMIT();
    }

    const uint32_t aRowB = (uint32_t)(wm * 64 + (lane & 15));
    const uint32_t aKH   = (lane & 16) ? 8u : 0u;
    const uint32_t bRowB = (uint32_t)(wn * 64 + (lane & 7) + ((lane & 16) ? 8 : 0));
    const uint32_t bKH   = (lane & 8) ? 8u : 0u;

    float acc[4][8][4];
    #pragma unroll
    for (int i = 0; i < 4; i++)
        #pragma unroll
        for (int j = 0; j < 8; j++)
            #pragma unroll
            for (int t = 0; t < 4; t++) acc[i][j][t] = 0.f;

    for (int g = 0; g < T; g++) {
        int kc = g & 7;
        CP_WAIT1();
        __syncthreads();

        if (g + 2 < T) {
            int g2 = g + 2;
            int mt2 = blockIdx.y + (g2 >> 3) * GY;
            const __nv_bfloat16* Ab = A + (size_t)mt2 * 128 * 256 + (g2 & 7) * 32;
            uint32_t st = aBase + (uint32_t)(g2 % 3) * BCH;
            #pragma unroll
            for (int j = 0; j < 4; j++) {
                int r = lr + j * 32;
                CP16(st + (uint32_t)(r * KP + lc) * 2, Ab + (size_t)r * 256 + lc);
            }
        }
        CP_COMMIT();

        const uint32_t aS = aBase + (uint32_t)(g % 3) * BCH;
        const uint32_t bS = sBase + (uint32_t)kc * BCH;
        #pragma unroll
        for (int ks = 0; ks < 2; ks++) {
            uint32_t af[4][4], bf[4][4];
            #pragma unroll
            for (int am = 0; am < 4; am++)
                ldsm4(af[am], aS + ((aRowB + am * 16) * KP + ks * 16 + aKH) * 2);
            #pragma unroll
            for (int gi = 0; gi < 4; gi++)
                ldsm4(bf[gi], bS + ((bRowB + gi * 16) * KP + ks * 16 + bKH) * 2);
            #pragma unroll
            for (int am = 0; am < 4; am++)
                #pragma unroll
                for (int nn = 0; nn < 8; nn++)
                    mma16816(acc[am][nn], af[am], &bf[nn >> 1][(nn & 1) * 2]);
        }

        if (kc == 7) {
            int bm = (blockIdx.y + (g >> 3) * GY) * 128;
            gemm_epilogue<EPI>(acc, sbias, residual, outv, Nc, bm, bn, wm, wn, lane);
            #pragma unroll
            for (int i = 0; i < 4; i++)
                #pragma unroll
                for (int j = 0; j < 8; j++)
                    #pragma unroll
                    for (int t = 0; t < 4; t++) acc[i][j][t] = 0.f;
        }
    }
}

// ---------------------------------------------------------------------------
// Streaming GEMM for fc2 (K=1024).
// ---------------------------------------------------------------------------
#define STAGE_B (2 * BCH)
#define B_OFF   BCH
#define ST_SMEM (4 * STAGE_B)

template<int EPI>
__global__ __launch_bounds__(128) void gemm_st(
    const __nv_bfloat16* __restrict__ A,
    const __nv_bfloat16* __restrict__ Bt,
    const float* __restrict__ bias,
    const float* __restrict__ residual,
    void* __restrict__ outv,
    int K, int Nc)
{
    extern __shared__ __align__(16) uint8_t smem[];
    __shared__ float sbias[128];

    const int tid = threadIdx.x;
    const int lane = tid & 31, wid = tid >> 5;
    const int wm = wid & 1;
    const int wn = wid >> 1;
    const int bn = blockIdx.x * 128, bm = blockIdx.y * 128;

    sbias[tid] = bias[bn + tid];

    const uint32_t sBase = smem_u32(smem);

    const int ldr0 = tid >> 2;
    const int ldc  = (tid & 3) * 8;

    const uint32_t aRowB = (uint32_t)(wm * 64 + (lane & 15));
    const uint32_t aKH   = (lane & 16) ? 8u : 0u;
    const uint32_t bRowB = (uint32_t)(wn * 64 + (lane & 7) + ((lane & 16) ? 8 : 0));
    const uint32_t bKH   = (lane & 8) ? 8u : 0u;

    float acc[4][8][4];
    #pragma unroll
    for (int i = 0; i < 4; i++)
        #pragma unroll
        for (int j = 0; j < 8; j++)
            #pragma unroll
            for (int t = 0; t < 4; t++) acc[i][j][t] = 0.f;

    const int nk = K >> 5;

    #pragma unroll
    for (int s = 0; s < 3; s++) {
        uint32_t st = sBase + s * STAGE_B;
        const __nv_bfloat16* Ab = A + (size_t)bm * K + s * 32;
        const __nv_bfloat16* Bb = Bt + (size_t)bn * K + s * 32;
        #pragma unroll
        for (int j = 0; j < 4; j++) {
            int r = ldr0 + j * 32;
            CP16(st + (uint32_t)(r * KP + ldc) * 2,         Ab + (size_t)r * K + ldc);
            CP16(st + B_OFF + (uint32_t)(r * KP + ldc) * 2, Bb + (size_t)r * K + ldc);
        }
        CP_COMMIT();
    }

    for (int kc = 0; kc < nk; kc++) {
        CP_WAIT2();
        __syncthreads();

        if (kc + 3 < nk) {
            uint32_t st = sBase + ((kc + 3) & 3) * STAGE_B;
            const __nv_bfloat16* Ab = A + (size_t)bm * K + (kc + 3) * 32;
            const __nv_bfloat16* Bb = Bt + (size_t)bn * K + (kc + 3) * 32;
            #pragma unroll
            for (int j = 0; j < 4; j++) {
                int r = ldr0 + j * 32;
                CP16(st + (uint32_t)(r * KP + ldc) * 2,         Ab + (size_t)r * K + ldc);
                CP16(st + B_OFF + (uint32_t)(r * KP + ldc) * 2, Bb + (size_t)r * K + ldc);
            }
        }
        CP_COMMIT();

        const uint32_t aS = sBase + (kc & 3) * STAGE_B;
        const uint32_t bS = aS + B_OFF;
        #pragma unroll
        for (int ks = 0; ks < 2; ks++) {
            uint32_t af[4][4], bf[4][4];
            #pragma unroll
            for (int am = 0; am < 4; am++)
                ldsm4(af[am], aS + ((aRowB + am * 16) * KP + ks * 16 + aKH) * 2);
            #pragma unroll
            for (int g = 0; g < 4; g++)
                ldsm4(bf[g], bS + ((bRowB + g * 16) * KP + ks * 16 + bKH) * 2);
            #pragma unroll
            for (int am = 0; am < 4; am++)
                #pragma unroll
                for (int nn = 0; nn < 8; nn++)
                    mma16816(acc[am][nn], af[am], &bf[nn >> 1][(nn & 1) * 2]);
        }
    }

    gemm_epilogue<EPI>(acc, sbias, residual, outv, Nc, bm, bn, wm, wn, lane);
}

// ---------------------------------------------------------------------------
// Fused-window attention with frag-ordered mask table.
// kb pad rows (49..63 per head) are zeroed: pad-col QK accs stay finite.
// ---------------------------------------------------------------------------
#define AQ_STR 40
#define AV_STR 72
#define ATTN_QS   0
#define ATTN_KB   (8 * 64 * AQ_STR)
#define ATTN_VT   (ATTN_KB + 8 * 64 * AQ_STR)
#define ATTN_SMEM ((ATTN_VT + 8 * 32 * AV_STR) * 2)

__global__ __launch_bounds__(256) void attn_kernel(
    const __nv_bfloat16* __restrict__ qkv,
    const float* __restrict__ amask,
    const float* __restrict__ temperature,
    __nv_bfloat16* __restrict__ o)
{
    extern __shared__ __align__(16) __nv_bfloat16 sm[];
    const int wi = blockIdx.x;
    const int tid = threadIdx.x;
    const int h = tid >> 5, lane = tid & 31;

    const float scale = expf(temperature[0]);
    const __nv_bfloat16* base = qkv + (size_t)wi * NSEQ * 768;

    {
        uint4 z = make_uint4(0, 0, 0, 0);
        uint4* v = (uint4*)(sm + ATTN_VT);
        for (int i = tid; i < 8 * 32 * AV_STR / 8; i += 256) v[i] = z;
        // zero kb pad rows 49..63 per head: 8 heads x 15 rows x 5 uint4
        for (int i = tid; i < 8 * 15 * 5; i += 256) {
            int hh = i / 75, rem = i - hh * 75;
            int row = 49 + rem / 5, q = rem % 5;
            *((uint4*)(sm + ATTN_KB + (hh * 64 + row) * AQ_STR) + q) = z;
        }
    }
    for (int idx = tid; idx < NSEQ * 96; idx += 256) {
        int r = idx / 96, u = idx - r * 96;
        int c0 = u * 8;
        uint4 val = *(const uint4*)(base + (size_t)r * 768 + c0);
        int ten = c0 >> 8;
        int within = c0 & 255;
        int hh = within >> 5, d = within & 31;
        if (ten == 0) {
            *(uint4*)(sm + ATTN_QS + hh * 64 * AQ_STR + r * AQ_STR + d) = val;
        } else if (ten == 1) {
            *(uint4*)(sm + ATTN_KB + hh * 64 * AQ_STR + r * AQ_STR + d) = val;
        } else {
            const __nv_bfloat16* e = (const __nv_bfloat16*)&val;
            __nv_bfloat16* vt = sm + ATTN_VT + hh * 32 * AV_STR;
            #pragma unroll
            for (int j = 0; j < 8; j++) vt[(d + j) * AV_STR + r] = e[j];
        }
    }
    __syncthreads();

    const uint32_t qB = smem_u32(sm + ATTN_QS + h * 64 * AQ_STR);
    const uint32_t kB = smem_u32(sm + ATTN_KB + h * 64 * AQ_STR);
    const uint32_t vB = smem_u32(sm + ATTN_VT + h * 32 * AV_STR);

    const uint32_t aRow = (uint32_t)(lane & 15);
    const uint32_t aKH  = (lane & 16) ? 8u : 0u;
    const uint32_t bRow = (uint32_t)((lane & 7) + ((lane & 16) ? 8 : 0));
    const uint32_t bKH  = (lane & 8) ? 8u : 0u;

    float acc[4][8][4];
    #pragma unroll
    for (int i = 0; i < 4; i++)
        #pragma unroll
        for (int j = 0; j < 8; j++)
            #pragma unroll
            for (int t = 0; t < 4; t++) acc[i][j][t] = 0.f;

    #pragma unroll
    for (int ks = 0; ks < 2; ks++) {
        uint32_t af[4][4], bf[4][4];
        #pragma unroll
        for (int am = 0; am < 4; am++)
            ldsm4(af[am], qB + ((aRow + am * 16) * AQ_STR + ks * 16 + aKH) * 2);
        #pragma unroll
        for (int g = 0; g < 4; g++)
            ldsm4(bf[g], kB + ((bRow + g * 16) * AQ_STR + ks * 16 + bKH) * 2);
        #pragma unroll
        for (int am = 0; am < 4; am++)
            #pragma unroll
            for (int nn = 0; nn < 8; nn++)
                mma16816(acc[am][nn], af[am], &bf[nn >> 1][(nn & 1) * 2]);
    }

    const float* tb = amask + (((size_t)(wi & 63) * 8 + h) << 12);
    uint32_t afP[4][4][4];

    #pragma unroll
    for (int am = 0; am < 4; am++) {
        #pragma unroll
        for (int half = 0; half < 2; half++) {
            const float4* tseg = (const float4*)(tb + (((am << 1) + half) << 9) + (lane << 4));
            float4 t0 = tseg[0], t1 = tseg[1], t2 = tseg[2], t3 = tseg[3];
            float tv[16] = {t0.x, t0.y, t0.z, t0.w, t1.x, t1.y, t1.z, t1.w,
                            t2.x, t2.y, t2.z, t2.w, t3.x, t3.y, t3.z, t3.w};
            float e[16];
            float mx = -3.402823466e38f;
            #pragma unroll
            for (int nt = 0; nt < 8; nt++) {
                #pragma unroll
                for (int j = 0; j < 2; j++) {
                    float s = fmaf(acc[am][nt][half * 2 + j], scale, tv[nt * 2 + j]);
                    e[nt * 2 + j] = s;
                    mx = fmaxf(mx, s);
                }
            }
            mx = fmaxf(mx, __shfl_xor_sync(0xffffffffu, mx, 1));
            mx = fmaxf(mx, __shfl_xor_sync(0xffffffffu, mx, 2));
            float sum = 0.f;
            #pragma unroll
            for (int i = 0; i < 16; i++) { e[i] = fexp(e[i] - mx); sum += e[i]; }
            sum += __shfl_xor_sync(0xffffffffu, sum, 1);
            sum += __shfl_xor_sync(0xffffffffu, sum, 2);
            float inv = 1.f / sum;
            #pragma unroll
            for (int ks = 0; ks < 4; ks++) {
                uint32_t lo = pack2(e[4 * ks] * inv,     e[4 * ks + 1] * inv);
                uint32_t hi = pack2(e[4 * ks + 2] * inv, e[4 * ks + 3] * inv);
                afP[am][ks][half]     = lo;
                afP[am][ks][2 + half] = hi;
            }
        }
    }

    float accP[4][4][4];
    #pragma unroll
    for (int i = 0; i < 4; i++)
        #pragma unroll
        for (int j = 0; j < 4; j++)
            #pragma unroll
            for (int t = 0; t < 4; t++) accP[i][j][t] = 0.f;

    #pragma unroll
    for (int ks = 0; ks < 4; ks++) {
        uint32_t bf[2][4];
        #pragma unroll
        for (int g = 0; g < 2; g++)
            ldsm4(bf[g], vB + ((bRow + g * 16) * AV_STR + ks * 16 + bKH) * 2);
        #pragma unroll
        for (int am = 0; am < 4; am++)
            #pragma unroll
            for (int nn = 0; nn < 4; nn++)
                mma16816(accP[am][nn], afP[am][ks], &bf[nn >> 1][(nn & 1) * 2]);
    }

    #pragma unroll
    for (int am = 0; am < 4; am++) {
        int n = am * 16 + (lane >> 2);
        int d0 = (lane & 3) * 2;
        #pragma unroll
        for (int nn = 0; nn < 4; nn++) {
            int d = d0 + nn * 8;
            if (n < NSEQ)
                *(uint32_t*)(o + (size_t)(wi * NSEQ + n) * C_DIM + h * HDIM + d)
                    = pack2(accP[am][nn][0], accP[am][nn][1]);
            if (n + 8 < NSEQ)
                *(uint32_t*)(o + (size_t)(wi * NSEQ + n + 8) * C_DIM + h * HDIM + d)
                    = pack2(accP[am][nn][2], accP[am][nn][3]);
        }
    }
}

// ---------------------------------------------------------------------------
extern "C" void kernel_launch(void* const* d_in, const int* in_sizes, int n_in,
                              void* d_out, int out_size)
{
    const float* x        = (const float*)d_in[0];
    const float* attn_msk = (const float*)d_in[1];
    const float* norm1_g  = (const float*)d_in[2];
    const float* norm1_b  = (const float*)d_in[3];
    const float* qkv_w    = (const float*)d_in[4];
    const float* qkv_b    = (const float*)d_in[5];
    const float* temp     = (const float*)d_in[6];
    const float* rel_tab  = (const float*)d_in[7];
    const float* proj_w   = (const float*)d_in[8];
    const float* proj_b   = (const float*)d_in[9];
    const float* norm2_g  = (const float*)d_in[10];
    const float* norm2_b  = (const float*)d_in[11];
    const float* fc1_w    = (const float*)d_in[12];
    const float* fc1_b    = (const float*)d_in[13];
    const float* fc2_w    = (const float*)d_in[14];
    const float* fc2_b    = (const float*)d_in[15];
    const int*   rel_idx  = (const int*)d_in[16];
    float* out = (float*)d_out;

    __nv_bfloat16 *zw, *qkv, *o, *hbuf, *fc1, *wqkvT, *wprojT, *wfc1T, *wfc2T;
    float *x2, *amask;
    cudaGetSymbolAddress((void**)&zw,    g_zw);
    cudaGetSymbolAddress((void**)&qkv,   g_qkv);
    cudaGetSymbolAddress((void**)&o,     g_o);
    cudaGetSymbolAddress((void**)&x2,    g_x2);
    cudaGetSymbolAddress((void**)&hbuf,  g_h);
    cudaGetSymbolAddress((void**)&fc1,   g_fc1);
    cudaGetSymbolAddress((void**)&wqkvT, g_wqkvT);
    cudaGetSymbolAddress((void**)&wprojT,g_wprojT);
    cudaGetSymbolAddress((void**)&wfc1T, g_wfc1T);
    cudaGetSymbolAddress((void**)&wfc2T, g_wfc2T);
    cudaGetSymbolAddress((void**)&amask, g_amask);

    static bool attr_done = false;
    if (!attr_done) {
        cudaFuncSetAttribute(gemm_pb<0>, cudaFuncAttributeMaxDynamicSharedMemorySize, PB_SMEM);
        cudaFuncSetAttribute(gemm_pb<1>, cudaFuncAttributeMaxDynamicSharedMemorySize, PB_SMEM);
        cudaFuncSetAttribute(gemm_pb<3>, cudaFuncAttributeMaxDynamicSharedMemorySize, PB_SMEM);
        cudaFuncSetAttribute(gemm_st<2>, cudaFuncAttributeMaxDynamicSharedMemorySize, ST_SMEM);
        cudaFuncSetAttribute(attn_kernel, cudaFuncAttributeMaxDynamicSharedMemorySize, ATTN_SMEM);
        attr_done = true;
    }

    // launch order: attn at index 3 for ncu capture
    prep_kernel<<<(PR4 + 255) / 256, 256>>>(qkv_w, proj_w, fc1_w, fc2_w,
                                            wqkvT, wprojT, wfc1T, wfc2T,
                                            rel_tab, rel_idx, attn_msk, amask);   // 0
    ln_kernel<<<M_TOK / 8, 256>>>(x, norm1_g, norm1_b, zw, 1);                     // 1
    gemm_pb<0><<<dim3(6, 48), 128, PB_SMEM>>>(zw, wqkvT, qkv_b, nullptr, qkv, 768);// 2
    attn_kernel<<<NWIN, 256, ATTN_SMEM>>>(qkv, amask, temp, o);                    // 3
    gemm_pb<3><<<dim3(2, 148), 128, PB_SMEM>>>(o, wprojT, proj_b, x, x2, 256);     // 4
    ln_kernel<<<M_TOK / 8, 256>>>(x2, norm2_g, norm2_b, hbuf, 0);                  // 5
    gemm_pb<1><<<dim3(8, 37), 128, PB_SMEM>>>(hbuf, wfc1T, fc1_b, nullptr, fc1, 1024); // 6
    gemm_st<2><<<dim3(2, NMT), 128, ST_SMEM>>>(fc1, wfc2T, fc2_b, x2, out, 1024, 256); // 7
}

// round 16
// speedup vs baseline: 1.2580x; 1.0763x over previous
#include <cuda_runtime.h>
#include <cuda_bf16.h>
#include <math.h>
#include <stdint.h>

// ---------------------------------------------------------------------------
// SwinTransformerBlock on GB300: persistent B-panel bf16 GEMMs + fused attn
// (attention split into head-groups for occupancy)
// ---------------------------------------------------------------------------

#define M_TOK   100352
#define C_DIM   256
#define NHEADS  8
#define HDIM    32
#define NWIN    2048
#define NSEQ    49
#define NMT     784

__device__ __nv_bfloat16 g_zw [(size_t)M_TOK * C_DIM];
__device__ __nv_bfloat16 g_qkv[(size_t)M_TOK * 768];
__device__ __nv_bfloat16 g_o  [(size_t)M_TOK * C_DIM];
__device__ float         g_x2 [(size_t)M_TOK * C_DIM];
__device__ __nv_bfloat16 g_h  [(size_t)M_TOK * C_DIM];
__device__ __nv_bfloat16 g_fc1[(size_t)M_TOK * 1024];
__device__ __nv_bfloat16 g_wqkvT[768 * 256];
__device__ __nv_bfloat16 g_wprojT[256 * 256];
__device__ __nv_bfloat16 g_wfc1T[1024 * 256];
__device__ __nv_bfloat16 g_wfc2T[256 * 1024];
__device__ float g_amask[64 * 8 * 8 * 512];

// ---------------------------------------------------------------------------
__device__ __forceinline__ uint32_t smem_u32(const void* p) {
    uint32_t a;
    asm("{ .reg .u64 t; cvta.to.shared.u64 t, %1; cvt.u32.u64 %0, t; }" : "=r"(a) : "l"(p));
    return a;
}
__device__ __forceinline__ void ldsm4(uint32_t* r, uint32_t addr) {
    asm volatile("ldmatrix.sync.aligned.m8n8.x4.shared.b16 {%0,%1,%2,%3}, [%4];"
                 : "=r"(r[0]), "=r"(r[1]), "=r"(r[2]), "=r"(r[3]) : "r"(addr));
}
__device__ __forceinline__ void mma16816(float* c, const uint32_t* a, const uint32_t* b) {
    asm volatile(
        "mma.sync.aligned.m16n8k16.row.col.f32.bf16.bf16.f32 "
        "{%0,%1,%2,%3}, {%4,%5,%6,%7}, {%8,%9}, {%0,%1,%2,%3};"
        : "+f"(c[0]), "+f"(c[1]), "+f"(c[2]), "+f"(c[3])
        : "r"(a[0]), "r"(a[1]), "r"(a[2]), "r"(a[3]), "r"(b[0]), "r"(b[1]));
}
__device__ __forceinline__ uint32_t pack2(float a, float b) {
    __nv_bfloat162 h = __floats2bfloat162_rn(a, b);
    return *(uint32_t*)&h;
}
__device__ __forceinline__ float fexp(float x) {
    float z = fmaxf(x * 1.4426950408889634f, -126.0f);
    float t = z + 12582912.0f;
    int   i = __float_as_int(t) - 0x4B400000;
    float f = z - (t - 12582912.0f);
    float p = 0.00961804886f;
    p = fmaf(p, f, 0.05550410866f);
    p = fmaf(p, f, 0.24022650696f);
    p = fmaf(p, f, 0.69314718056f);
    p = fmaf(p, f, 1.0f);
    return __int_as_float(__float_as_int(p) + (i << 23));
}
#define CP16(dst, src) asm volatile("cp.async.cg.shared.global [%0], [%1], 16;" :: "r"(dst), "l"(src))
#define CP_COMMIT()    asm volatile("cp.async.commit_group;" ::: "memory")
#define CP_WAIT1()     asm volatile("cp.async.wait_group 1;" ::: "memory")
#define CP_WAIT2()     asm volatile("cp.async.wait_group 2;" ::: "memory")

// ---------------------------------------------------------------------------
// prep: weight transposes + amask table (range split).
// ---------------------------------------------------------------------------
__device__ __forceinline__ void wconv_elem(int id, const float* in,
                                           __nv_bfloat16* out, int K, int N)
{
    int n = id / K, k = id - n * K;
    out[id] = __float2bfloat16(in[(size_t)k * N + n]);
}

#define PR0 (256 * 768)
#define PR1 (PR0 + 256 * 256)
#define PR2 (PR1 + 256 * 1024)
#define PR3 (PR2 + 1024 * 256)
#define PR4 (PR3 + 64 * 8 * 8 * 512)

__global__ void prep_kernel(
    const float* __restrict__ qkv_w, const float* __restrict__ proj_w,
    const float* __restrict__ fc1_w, const float* __restrict__ fc2_w,
    __nv_bfloat16* __restrict__ wqkvT, __nv_bfloat16* __restrict__ wprojT,
    __nv_bfloat16* __restrict__ wfc1T, __nv_bfloat16* __restrict__ wfc2T,
    const float* __restrict__ rel_table, const int* __restrict__ rel_idx,
    const float* __restrict__ attn_mask, float* __restrict__ amask)
{
    int gid = blockIdx.x * 256 + threadIdx.x;
    if (gid < PR0) {
        wconv_elem(gid, qkv_w, wqkvT, 256, 768);
    } else if (gid < PR1) {
        wconv_elem(gid - PR0, proj_w, wprojT, 256, 256);
    } else if (gid < PR2) {
        wconv_elem(gid - PR1, fc1_w, wfc1T, 256, 1024);
    } else if (gid < PR3) {
        wconv_elem(gid - PR2, fc2_w, wfc2T, 1024, 256);
    } else if (gid < PR4) {
        int idx = gid - PR3;
        int i    = idx & 15;
        int lane = (idx >> 4) & 31;
        int seg  = (idx >> 9) & 7;
        int h    = (idx >> 12) & 7;
        int wt   = idx >> 15;
        int am = seg >> 1, half = seg & 1;
        int row = am * 16 + (lane >> 2) + half * 8;
        int col = (i >> 1) * 8 + (lane & 3) * 2 + (i & 1);
        float v = -3.402823466e38f;
        if (row < NSEQ && col < NSEQ && row != col)
            v = rel_table[rel_idx[row * NSEQ + col] * NHEADS + h]
              + attn_mask[wt * NSEQ * NSEQ + row * NSEQ + col];
        amask[idx] = v;
    }
}

// ---------------------------------------------------------------------------
// LayerNorm: warp-per-token. 8 tokens / block.
// ---------------------------------------------------------------------------
__global__ __launch_bounds__(256) void ln_kernel(
    const float* __restrict__ x,
    const float* __restrict__ gamma,
    const float* __restrict__ beta,
    __nv_bfloat16* __restrict__ out,
    int shifted)
{
    int wid = threadIdx.x >> 5, lane = threadIdx.x & 31;
    int t = blockIdx.x * 8 + wid;
    int src;
    if (shifted) {
        int wi  = t / NSEQ;
        int pos = t - wi * NSEQ;
        int b    = wi >> 6;
        int wrem = wi & 63;
        int hs = (wrem >> 3) * 7 + pos / 7;
        int ws = (wrem & 7) * 7 + pos % 7;
        int sh = hs + 3; if (sh >= 56) sh -= 56;
        int sw = ws + 3; if (sw >= 56) sw -= 56;
        src = b * 3136 + sh * 56 + sw;
    } else {
        src = t;
    }
    const float* row = x + (size_t)src * C_DIM + lane * 8;
    float4 v0 = *(const float4*)(row);
    float4 v1 = *(const float4*)(row + 4);
    float v[8] = {v0.x, v0.y, v0.z, v0.w, v1.x, v1.y, v1.z, v1.w};
    float s = 0.f, s2 = 0.f;
    #pragma unroll
    for (int i = 0; i < 8; i++) { s += v[i]; s2 += v[i] * v[i]; }
    #pragma unroll
    for (int off = 16; off; off >>= 1) {
        s  += __shfl_xor_sync(0xffffffffu, s,  off);
        s2 += __shfl_xor_sync(0xffffffffu, s2, off);
    }
    float mean = s * (1.f / 256.f);
    float var  = s2 * (1.f / 256.f) - mean * mean;
    float r = rsqrtf(var + 1e-6f);
    const float* g4 = gamma + lane * 8;
    const float* b4 = beta + lane * 8;
    uint32_t o4[4];
    #pragma unroll
    for (int i = 0; i < 4; i++) {
        float a0 = (v[2*i]   - mean) * r * g4[2*i]   + b4[2*i];
        float a1 = (v[2*i+1] - mean) * r * g4[2*i+1] + b4[2*i+1];
        o4[i] = pack2(a0, a1);
    }
    *(uint4*)(out + (size_t)t * C_DIM + lane * 8) = *(uint4*)o4;
}

// ---------------------------------------------------------------------------
// Shared GEMM epilogue.
// ---------------------------------------------------------------------------
template<int EPI>
__device__ __forceinline__ void gemm_epilogue(
    float acc[4][8][4], const float* sbias, const float* residual,
    void* outv, int Nc, int bm, int bn, int wm, int wn, int lane)
{
    const int n0 = bn + wn * 64 + (lane & 3) * 2;
    const int m0 = bm + wm * 64 + (lane >> 2);

    #pragma unroll
    for (int am = 0; am < 4; am++) {
        int mA = m0 + am * 16;
        int dstA = mA, dstB = mA + 8;
        if (EPI == 3) {
            #pragma unroll
            for (int h = 0; h < 2; h++) {
                int m = mA + h * 8;
                int wi  = m / NSEQ;
                int pos = m - wi * NSEQ;
                int b    = wi >> 6;
                int wrem = wi & 63;
                int hs = (wrem >> 3) * 7 + pos / 7;
                int ws = (wrem & 7) * 7 + pos % 7;
                int dh = hs + 3; if (dh >= 56) dh -= 56;
                int dw = ws + 3; if (dw >= 56) dw -= 56;
                int d = b * 3136 + dh * 56 + dw;
                if (h == 0) dstA = d; else dstB = d;
            }
        }
        #pragma unroll
        for (int nn = 0; nn < 8; nn++) {
            int col = n0 + nn * 8;
            float b0 = sbias[col - bn], b1 = sbias[col - bn + 1];
            float c0 = acc[am][nn][0] + b0, c1 = acc[am][nn][1] + b1;
            float c2 = acc[am][nn][2] + b0, c3 = acc[am][nn][3] + b1;
            if (EPI == 1) {
                c0 = c0 * 0.5f * (1.f + erff(c0 * 0.70710678118654752f));
                c1 = c1 * 0.5f * (1.f + erff(c1 * 0.70710678118654752f));
                c2 = c2 * 0.5f * (1.f + erff(c2 * 0.70710678118654752f));
                c3 = c3 * 0.5f * (1.f + erff(c3 * 0.70710678118654752f));
            }
            if (EPI == 0 || EPI == 1) {
                __nv_bfloat16* out = (__nv_bfloat16*)outv;
                *(uint32_t*)(out + (size_t)mA * Nc + col)       = pack2(c0, c1);
                *(uint32_t*)(out + (size_t)(mA + 8) * Nc + col) = pack2(c2, c3);
            } else {
                float* out = (float*)outv;
                float2 r0 = *(const float2*)(residual + (size_t)dstA * Nc + col);
                float2 r1 = *(const float2*)(residual + (size_t)dstB * Nc + col);
                *(float2*)(out + (size_t)dstA * Nc + col) = make_float2(c0 + r0.x, c1 + r0.y);
                *(float2*)(out + (size_t)dstB * Nc + col) = make_float2(c2 + r1.x, c3 + r1.y);
            }
        }
    }
}

// ---------------------------------------------------------------------------
// Persistent B-panel GEMM (K=256).
// ---------------------------------------------------------------------------
#define KP 40
#define BCH (128 * KP * 2)
#define PB_SMEM (8 * BCH + 3 * BCH)

template<int EPI>
__global__ __launch_bounds__(128) void gemm_pb(
    const __nv_bfloat16* __restrict__ A,
    const __nv_bfloat16* __restrict__ Bt,
    const float* __restrict__ bias,
    const float* __restrict__ residual,
    void* __restrict__ outv,
    int Nc)
{
    extern __shared__ __align__(16) uint8_t smem[];
    __shared__ float sbias[128];

    const int tid = threadIdx.x;
    const int lane = tid & 31, wid = tid >> 5;
    const int wm = wid & 1;
    const int wn = wid >> 1;
    const int bn = blockIdx.x * 128;
    const int GY = gridDim.y;

    sbias[tid] = bias[bn + tid];

    const uint32_t sBase = smem_u32(smem);
    const uint32_t aBase = sBase + 8 * BCH;

    const int lr = tid >> 2;
    const int lc = (tid & 3) * 8;

    {
        const __nv_bfloat16* Bb = Bt + (size_t)bn * 256;
        #pragma unroll
        for (int ch = 0; ch < 8; ch++)
            #pragma unroll
            for (int j = 0; j < 4; j++) {
                int r = lr + j * 32;
                CP16(sBase + ch * BCH + (uint32_t)(r * KP + lc) * 2,
                     Bb + (size_t)r * 256 + ch * 32 + lc);
            }
        CP_COMMIT();
    }

    const int nTiles = (NMT - blockIdx.y + GY - 1) / GY;
    const int T = nTiles * 8;

    #pragma unroll
    for (int s = 0; s < 2; s++) {
        if (s < T) {
            int mt = blockIdx.y + (s >> 3) * GY;
            const __nv_bfloat16* Ab = A + (size_t)mt * 128 * 256 + (s & 7) * 32;
            #pragma unroll
            for (int j = 0; j < 4; j++) {
                int r = lr + j * 32;
                CP16(aBase + s * BCH + (uint32_t)(r * KP + lc) * 2, Ab + (size_t)r * 256 + lc);
            }
        }
        CP_COMMIT();
    }

    const uint32_t aRowB = (uint32_t)(wm * 64 + (lane & 15));
    const uint32_t aKH   = (lane & 16) ? 8u : 0u;
    const uint32_t bRowB = (uint32_t)(wn * 64 + (lane & 7) + ((lane & 16) ? 8 : 0));
    const uint32_t bKH   = (lane & 8) ? 8u : 0u;

    float acc[4][8][4];
    #pragma unroll
    for (int i = 0; i < 4; i++)
        #pragma unroll
        for (int j = 0; j < 8; j++)
            #pragma unroll
            for (int t = 0; t < 4; t++) acc[i][j][t] = 0.f;

    for (int g = 0; g < T; g++) {
        int kc = g & 7;
        CP_WAIT1();
        __syncthreads();

        if (g + 2 < T) {
            int g2 = g + 2;
            int mt2 = blockIdx.y + (g2 >> 3) * GY;
            const __nv_bfloat16* Ab = A + (size_t)mt2 * 128 * 256 + (g2 & 7) * 32;
            uint32_t st = aBase + (uint32_t)(g2 % 3) * BCH;
            #pragma unroll
            for (int j = 0; j < 4; j++) {
                int r = lr + j * 32;
                CP16(st + (uint32_t)(r * KP + lc) * 2, Ab + (size_t)r * 256 + lc);
            }
        }
        CP_COMMIT();

        const uint32_t aS = aBase + (uint32_t)(g % 3) * BCH;
        const uint32_t bS = sBase + (uint32_t)kc * BCH;
        #pragma unroll
        for (int ks = 0; ks < 2; ks++) {
            uint32_t af[4][4], bf[4][4];
            #pragma unroll
            for (int am = 0; am < 4; am++)
                ldsm4(af[am], aS + ((aRowB + am * 16) * KP + ks * 16 + aKH) * 2);
            #pragma unroll
            for (int gi = 0; gi < 4; gi++)
                ldsm4(bf[gi], bS + ((bRowB + gi * 16) * KP + ks * 16 + bKH) * 2);
            #pragma unroll
            for (int am = 0; am < 4; am++)
                #pragma unroll
                for (int nn = 0; nn < 8; nn++)
                    mma16816(acc[am][nn], af[am], &bf[nn >> 1][(nn & 1) * 2]);
        }

        if (kc == 7) {
            int bm = (blockIdx.y + (g >> 3) * GY) * 128;
            gemm_epilogue<EPI>(acc, sbias, residual, outv, Nc, bm, bn, wm, wn, lane);
            #pragma unroll
            for (int i = 0; i < 4; i++)
                #pragma unroll
                for (int j = 0; j < 8; j++)
                    #pragma unroll
                    for (int t = 0; t < 4; t++) acc[i][j][t] = 0.f;
        }
    }
}

// ---------------------------------------------------------------------------
// Streaming GEMM for fc2 (K=1024).
// ---------------------------------------------------------------------------
#define STAGE_B (2 * BCH)
#define B_OFF   BCH
#define ST_SMEM (4 * STAGE_B)

template<int EPI>
__global__ __launch_bounds__(128) void gemm_st(
    const __nv_bfloat16* __restrict__ A,
    const __nv_bfloat16* __restrict__ Bt,
    const float* __restrict__ bias,
    const float* __restrict__ residual,
    void* __restrict__ outv,
    int K, int Nc)
{
    extern __shared__ __align__(16) uint8_t smem[];
    __shared__ float sbias[128];

    const int tid = threadIdx.x;
    const int lane = tid & 31, wid = tid >> 5;
    const int wm = wid & 1;
    const int wn = wid >> 1;
    const int bn = blockIdx.x * 128, bm = blockIdx.y * 128;

    sbias[tid] = bias[bn + tid];

    const uint32_t sBase = smem_u32(smem);

    const int ldr0 = tid >> 2;
    const int ldc  = (tid & 3) * 8;

    const uint32_t aRowB = (uint32_t)(wm * 64 + (lane & 15));
    const uint32_t aKH   = (lane & 16) ? 8u : 0u;
    const uint32_t bRowB = (uint32_t)(wn * 64 + (lane & 7) + ((lane & 16) ? 8 : 0));
    const uint32_t bKH   = (lane & 8) ? 8u : 0u;

    float acc[4][8][4];
    #pragma unroll
    for (int i = 0; i < 4; i++)
        #pragma unroll
        for (int j = 0; j < 8; j++)
            #pragma unroll
            for (int t = 0; t < 4; t++) acc[i][j][t] = 0.f;

    const int nk = K >> 5;

    #pragma unroll
    for (int s = 0; s < 3; s++) {
        uint32_t st = sBase + s * STAGE_B;
        const __nv_bfloat16* Ab = A + (size_t)bm * K + s * 32;
        const __nv_bfloat16* Bb = Bt + (size_t)bn * K + s * 32;
        #pragma unroll
        for (int j = 0; j < 4; j++) {
            int r = ldr0 + j * 32;
            CP16(st + (uint32_t)(r * KP + ldc) * 2,         Ab + (size_t)r * K + ldc);
            CP16(st + B_OFF + (uint32_t)(r * KP + ldc) * 2, Bb + (size_t)r * K + ldc);
        }
        CP_COMMIT();
    }

    for (int kc = 0; kc < nk; kc++) {
        CP_WAIT2();
        __syncthreads();

        if (kc + 3 < nk) {
            uint32_t st = sBase + ((kc + 3) & 3) * STAGE_B;
            const __nv_bfloat16* Ab = A + (size_t)bm * K + (kc + 3) * 32;
            const __nv_bfloat16* Bb = Bt + (size_t)bn * K + (kc + 3) * 32;
            #pragma unroll
            for (int j = 0; j < 4; j++) {
                int r = ldr0 + j * 32;
                CP16(st + (uint32_t)(r * KP + ldc) * 2,         Ab + (size_t)r * K + ldc);
                CP16(st + B_OFF + (uint32_t)(r * KP + ldc) * 2, Bb + (size_t)r * K + ldc);
            }
        }
        CP_COMMIT();

        const uint32_t aS = sBase + (kc & 3) * STAGE_B;
        const uint32_t bS = aS + B_OFF;
        #pragma unroll
        for (int ks = 0; ks < 2; ks++) {
            uint32_t af[4][4], bf[4][4];
            #pragma unroll
            for (int am = 0; am < 4; am++)
                ldsm4(af[am], aS + ((aRowB + am * 16) * KP + ks * 16 + aKH) * 2);
            #pragma unroll
            for (int g = 0; g < 4; g++)
                ldsm4(bf[g], bS + ((bRowB + g * 16) * KP + ks * 16 + bKH) * 2);
            #pragma unroll
            for (int am = 0; am < 4; am++)
                #pragma unroll
                for (int nn = 0; nn < 8; nn++)
                    mma16816(acc[am][nn], af[am], &bf[nn >> 1][(nn & 1) * 2]);
        }
    }

    gemm_epilogue<EPI>(acc, sbias, residual, outv, Nc, bm, bn, wm, wn, lane);
}

// ---------------------------------------------------------------------------
// Fused attention, head-group split: block = (window, head-group of 4).
// 128 threads (4 warps = 4 heads); smem 59.4KB -> 3 CTAs/SM.
// ---------------------------------------------------------------------------
#define AQ_STR 40
#define AV_STR 72
#define HG      4                              // heads per block
#define ATTN_QS   0
#define ATTN_KB   (HG * 64 * AQ_STR)
#define ATTN_VT   (ATTN_KB + HG * 64 * AQ_STR)
#define ATTN_SMEM ((ATTN_VT + HG * 32 * AV_STR) * 2)

__global__ __launch_bounds__(128) void attn_kernel(
    const __nv_bfloat16* __restrict__ qkv,
    const float* __restrict__ amask,
    const float* __restrict__ temperature,
    __nv_bfloat16* __restrict__ o)
{
    extern __shared__ __align__(16) __nv_bfloat16 sm[];
    const int wi = blockIdx.x;
    const int hg = blockIdx.y;                 // head group 0/1
    const int tid = threadIdx.x;
    const int hl = tid >> 5, lane = tid & 31;  // local head = warp
    const int h = hg * HG + hl;                // global head

    const float scale = expf(temperature[0]);
    const __nv_bfloat16* base = qkv + (size_t)wi * NSEQ * 768;

    {
        uint4 z = make_uint4(0, 0, 0, 0);
        uint4* v = (uint4*)(sm + ATTN_VT);
        for (int i = tid; i < HG * 32 * AV_STR / 8; i += 128) v[i] = z;
        // zero kb pad rows 49..63 per local head: HG x 15 rows x 5 uint4
        for (int i = tid; i < HG * 15 * 5; i += 128) {
            int hh = i / 75, rem = i - hh * 75;
            int row = 49 + rem / 5, q = rem % 5;
            *((uint4*)(sm + ATTN_KB + (hh * 64 + row) * AQ_STR) + q) = z;
        }
    }
    // load q/k/v for this head group: 49 rows x 3 tensors x 4 heads x 4 uint4
    for (int idx = tid; idx < NSEQ * 48; idx += 128) {
        int r = idx / 48, u = idx - r * 48;
        int ten = u >> 4;                 // 0=q 1=k 2=v
        int seg = u & 15;
        int hh  = seg >> 2;               // local head
        int cw  = (seg & 3) * 8;          // col within head
        uint4 val = *(const uint4*)(base + (size_t)r * 768 + ten * 256 + hg * 128 + hh * 32 + cw);
        if (ten == 0) {
            *(uint4*)(sm + ATTN_QS + (hh * 64 + r) * AQ_STR + cw) = val;
        } else if (ten == 1) {
            *(uint4*)(sm + ATTN_KB + (hh * 64 + r) * AQ_STR + cw) = val;
        } else {
            const __nv_bfloat16* e = (const __nv_bfloat16*)&val;
            __nv_bfloat16* vt = sm + ATTN_VT + hh * 32 * AV_STR;
            #pragma unroll
            for (int j = 0; j < 8; j++) vt[(cw + j) * AV_STR + r] = e[j];
        }
    }
    __syncthreads();

    const uint32_t qB = smem_u32(sm + ATTN_QS + hl * 64 * AQ_STR);
    const uint32_t kB = smem_u32(sm + ATTN_KB + hl * 64 * AQ_STR);
    const uint32_t vB = smem_u32(sm + ATTN_VT + hl * 32 * AV_STR);

    const uint32_t aRow = (uint32_t)(lane & 15);
    const uint32_t aKH  = (lane & 16) ? 8u : 0u;
    const uint32_t bRow = (uint32_t)((lane & 7) + ((lane & 16) ? 8 : 0));
    const uint32_t bKH  = (lane & 8) ? 8u : 0u;

    float acc[4][8][4];
    #pragma unroll
    for (int i = 0; i < 4; i++)
        #pragma unroll
        for (int j = 0; j < 8; j++)
            #pragma unroll
            for (int t = 0; t < 4; t++) acc[i][j][t] = 0.f;

    #pragma unroll
    for (int ks = 0; ks < 2; ks++) {
        uint32_t af[4][4], bf[4][4];
        #pragma unroll
        for (int am = 0; am < 4; am++)
            ldsm4(af[am], qB + ((aRow + am * 16) * AQ_STR + ks * 16 + aKH) * 2);
        #pragma unroll
        for (int g = 0; g < 4; g++)
            ldsm4(bf[g], kB + ((bRow + g * 16) * AQ_STR + ks * 16 + bKH) * 2);
        #pragma unroll
        for (int am = 0; am < 4; am++)
            #pragma unroll
            for (int nn = 0; nn < 8; nn++)
                mma16816(acc[am][nn], af[am], &bf[nn >> 1][(nn & 1) * 2]);
    }

    const float* tb = amask + (((size_t)(wi & 63) * 8 + h) << 12);
    uint32_t afP[4][4][4];

    #pragma unroll
    for (int am = 0; am < 4; am++) {
        #pragma unroll
        for (int half = 0; half < 2; half++) {
            const float4* tseg = (const float4*)(tb + (((am << 1) + half) << 9) + (lane << 4));
            float4 t0 = tseg[0], t1 = tseg[1], t2 = tseg[2], t3 = tseg[3];
            float tv[16] = {t0.x, t0.y, t0.z, t0.w, t1.x, t1.y, t1.z, t1.w,
                            t2.x, t2.y, t2.z, t2.w, t3.x, t3.y, t3.z, t3.w};
            float e[16];
            float mx = -3.402823466e38f;
            #pragma unroll
            for (int nt = 0; nt < 8; nt++) {
                #pragma unroll
                for (int j = 0; j < 2; j++) {
                    float s = fmaf(acc[am][nt][half * 2 + j], scale, tv[nt * 2 + j]);
                    e[nt * 2 + j] = s;
                    mx = fmaxf(mx, s);
                }
            }
            mx = fmaxf(mx, __shfl_xor_sync(0xffffffffu, mx, 1));
            mx = fmaxf(mx, __shfl_xor_sync(0xffffffffu, mx, 2));
            float sum = 0.f;
            #pragma unroll
            for (int i = 0; i < 16; i++) { e[i] = fexp(e[i] - mx); sum += e[i]; }
            sum += __shfl_xor_sync(0xffffffffu, sum, 1);
            sum += __shfl_xor_sync(0xffffffffu, sum, 2);
            float inv = 1.f / sum;
            #pragma unroll
            for (int ks = 0; ks < 4; ks++) {
                uint32_t lo = pack2(e[4 * ks] * inv,     e[4 * ks + 1] * inv);
                uint32_t hi = pack2(e[4 * ks + 2] * inv, e[4 * ks + 3] * inv);
                afP[am][ks][half]     = lo;
                afP[am][ks][2 + half] = hi;
            }
        }
    }

    float accP[4][4][4];
    #pragma unroll
    for (int i = 0; i < 4; i++)
        #pragma unroll
        for (int j = 0; j < 4; j++)
            #pragma unroll
            for (int t = 0; t < 4; t++) accP[i][j][t] = 0.f;

    #pragma unroll
    for (int ks = 0; ks < 4; ks++) {
        uint32_t bf[2][4];
        #pragma unroll
        for (int g = 0; g < 2; g++)
            ldsm4(bf[g], vB + ((bRow + g * 16) * AV_STR + ks * 16 + bKH) * 2);
        #pragma unroll
        for (int am = 0; am < 4; am++)
            #pragma unroll
            for (int nn = 0; nn < 4; nn++)
                mma16816(accP[am][nn], afP[am][ks], &bf[nn >> 1][(nn & 1) * 2]);
    }

    #pragma unroll
    for (int am = 0; am < 4; am++) {
        int n = am * 16 + (lane >> 2);
        int d0 = (lane & 3) * 2;
        #pragma unroll
        for (int nn = 0; nn < 4; nn++) {
            int d = d0 + nn * 8;
            if (n < NSEQ)
                *(uint32_t*)(o + (size_t)(wi * NSEQ + n) * C_DIM + h * HDIM + d)
                    = pack2(accP[am][nn][0], accP[am][nn][1]);
            if (n + 8 < NSEQ)
                *(uint32_t*)(o + (size_t)(wi * NSEQ + n + 8) * C_DIM + h * HDIM + d)
                    = pack2(accP[am][nn][2], accP[am][nn][3]);
        }
    }
}

// ---------------------------------------------------------------------------
extern "C" void kernel_launch(void* const* d_in, const int* in_sizes, int n_in,
                              void* d_out, int out_size)
{
    const float* x        = (const float*)d_in[0];
    const float* attn_msk = (const float*)d_in[1];
    const float* norm1_g  = (const float*)d_in[2];
    const float* norm1_b  = (const float*)d_in[3];
    const float* qkv_w    = (const float*)d_in[4];
    const float* qkv_b    = (const float*)d_in[5];
    const float* temp     = (const float*)d_in[6];
    const float* rel_tab  = (const float*)d_in[7];
    const float* proj_w   = (const float*)d_in[8];
    const float* proj_b   = (const float*)d_in[9];
    const float* norm2_g  = (const float*)d_in[10];
    const float* norm2_b  = (const float*)d_in[11];
    const float* fc1_w    = (const float*)d_in[12];
    const float* fc1_b    = (const float*)d_in[13];
    const float* fc2_w    = (const float*)d_in[14];
    const float* fc2_b    = (const float*)d_in[15];
    const int*   rel_idx  = (const int*)d_in[16];
    float* out = (float*)d_out;

    __nv_bfloat16 *zw, *qkv, *o, *hbuf, *fc1, *wqkvT, *wprojT, *wfc1T, *wfc2T;
    float *x2, *amask;
    cudaGetSymbolAddress((void**)&zw,    g_zw);
    cudaGetSymbolAddress((void**)&qkv,   g_qkv);
    cudaGetSymbolAddress((void**)&o,     g_o);
    cudaGetSymbolAddress((void**)&x2,    g_x2);
    cudaGetSymbolAddress((void**)&hbuf,  g_h);
    cudaGetSymbolAddress((void**)&fc1,   g_fc1);
    cudaGetSymbolAddress((void**)&wqkvT, g_wqkvT);
    cudaGetSymbolAddress((void**)&wprojT,g_wprojT);
    cudaGetSymbolAddress((void**)&wfc1T, g_wfc1T);
    cudaGetSymbolAddress((void**)&wfc2T, g_wfc2T);
    cudaGetSymbolAddress((void**)&amask, g_amask);

    static bool attr_done = false;
    if (!attr_done) {
        cudaFuncSetAttribute(gemm_pb<0>, cudaFuncAttributeMaxDynamicSharedMemorySize, PB_SMEM);
        cudaFuncSetAttribute(gemm_pb<1>, cudaFuncAttributeMaxDynamicSharedMemorySize, PB_SMEM);
        cudaFuncSetAttribute(gemm_pb<3>, cudaFuncAttributeMaxDynamicSharedMemorySize, PB_SMEM);
        cudaFuncSetAttribute(gemm_st<2>, cudaFuncAttributeMaxDynamicSharedMemorySize, ST_SMEM);
        cudaFuncSetAttribute(attn_kernel, cudaFuncAttributeMaxDynamicSharedMemorySize, ATTN_SMEM);
        attr_done = true;
    }

    prep_kernel<<<(PR4 + 255) / 256, 256>>>(qkv_w, proj_w, fc1_w, fc2_w,
                                            wqkvT, wprojT, wfc1T, wfc2T,
                                            rel_tab, rel_idx, attn_msk, amask);   // 0
    ln_kernel<<<M_TOK / 8, 256>>>(x, norm1_g, norm1_b, zw, 1);                     // 1
    gemm_pb<0><<<dim3(6, 48), 128, PB_SMEM>>>(zw, wqkvT, qkv_b, nullptr, qkv, 768);// 2
    attn_kernel<<<dim3(NWIN, 2), 128, ATTN_SMEM>>>(qkv, amask, temp, o);           // 3
    gemm_pb<3><<<dim3(2, 148), 128, PB_SMEM>>>(o, wprojT, proj_b, x, x2, 256);     // 4
    ln_kernel<<<M_TOK / 8, 256>>>(x2, norm2_g, norm2_b, hbuf, 0);                  // 5
    gemm_pb<1><<<dim3(8, 37), 128, PB_SMEM>>>(hbuf, wfc1T, fc1_b, nullptr, fc1, 1024); // 6
    gemm_st<2><<<dim3(2, NMT), 128, ST_SMEM>>>(fc1, wfc2T, fc2_b, x2, out, 1024, 256); // 7
}

// round 17
// speedup vs baseline: 1.2673x; 1.0074x over previous
#include <cuda_runtime.h>
#include <cuda_bf16.h>
#include <math.h>
#include <stdint.h>

// ---------------------------------------------------------------------------
// SwinTransformerBlock on GB300: persistent B-panel bf16 GEMMs + fused attn
// (attention: per-am-tile pipeline, 4 CTAs/SM)
// ---------------------------------------------------------------------------

#define M_TOK   100352
#define C_DIM   256
#define NHEADS  8
#define HDIM    32
#define NWIN    2048
#define NSEQ    49
#define NMT     784

__device__ __nv_bfloat16 g_zw [(size_t)M_TOK * C_DIM];
__device__ __nv_bfloat16 g_qkv[(size_t)M_TOK * 768];
__device__ __nv_bfloat16 g_o  [(size_t)M_TOK * C_DIM];
__device__ float         g_x2 [(size_t)M_TOK * C_DIM];
__device__ __nv_bfloat16 g_h  [(size_t)M_TOK * C_DIM];
__device__ __nv_bfloat16 g_fc1[(size_t)M_TOK * 1024];
__device__ __nv_bfloat16 g_wqkvT[768 * 256];
__device__ __nv_bfloat16 g_wprojT[256 * 256];
__device__ __nv_bfloat16 g_wfc1T[1024 * 256];
__device__ __nv_bfloat16 g_wfc2T[256 * 1024];
__device__ float g_amask[64 * 8 * 8 * 512];

// ---------------------------------------------------------------------------
__device__ __forceinline__ uint32_t smem_u32(const void* p) {
    uint32_t a;
    asm("{ .reg .u64 t; cvta.to.shared.u64 t, %1; cvt.u32.u64 %0, t; }" : "=r"(a) : "l"(p));
    return a;
}
__device__ __forceinline__ void ldsm4(uint32_t* r, uint32_t addr) {
    asm volatile("ldmatrix.sync.aligned.m8n8.x4.shared.b16 {%0,%1,%2,%3}, [%4];"
                 : "=r"(r[0]), "=r"(r[1]), "=r"(r[2]), "=r"(r[3]) : "r"(addr));
}
__device__ __forceinline__ void mma16816(float* c, const uint32_t* a, const uint32_t* b) {
    asm volatile(
        "mma.sync.aligned.m16n8k16.row.col.f32.bf16.bf16.f32 "
        "{%0,%1,%2,%3}, {%4,%5,%6,%7}, {%8,%9}, {%0,%1,%2,%3};"
        : "+f"(c[0]), "+f"(c[1]), "+f"(c[2]), "+f"(c[3])
        : "r"(a[0]), "r"(a[1]), "r"(a[2]), "r"(a[3]), "r"(b[0]), "r"(b[1]));
}
__device__ __forceinline__ uint32_t pack2(float a, float b) {
    __nv_bfloat162 h = __floats2bfloat162_rn(a, b);
    return *(uint32_t*)&h;
}
__device__ __forceinline__ float fexp(float x) {
    float z = fmaxf(x * 1.4426950408889634f, -126.0f);
    float t = z + 12582912.0f;
    int   i = __float_as_int(t) - 0x4B400000;
    float f = z - (t - 12582912.0f);
    float p = 0.00961804886f;
    p = fmaf(p, f, 0.05550410866f);
    p = fmaf(p, f, 0.24022650696f);
    p = fmaf(p, f, 0.69314718056f);
    p = fmaf(p, f, 1.0f);
    return __int_as_float(__float_as_int(p) + (i << 23));
}
#define CP16(dst, src) asm volatile("cp.async.cg.shared.global [%0], [%1], 16;" :: "r"(dst), "l"(src))
#define CP_COMMIT()    asm volatile("cp.async.commit_group;" ::: "memory")
#define CP_WAIT1()     asm volatile("cp.async.wait_group 1;" ::: "memory")

// ---------------------------------------------------------------------------
// prep: weight transposes + amask table (range split).
// ---------------------------------------------------------------------------
__device__ __forceinline__ void wconv_elem(int id, const float* in,
                                           __nv_bfloat16* out, int K, int N)
{
    int n = id / K, k = id - n * K;
    out[id] = __float2bfloat16(in[(size_t)k * N + n]);
}

#define PR0 (256 * 768)
#define PR1 (PR0 + 256 * 256)
#define PR2 (PR1 + 256 * 1024)
#define PR3 (PR2 + 1024 * 256)
#define PR4 (PR3 + 64 * 8 * 8 * 512)

__global__ void prep_kernel(
    const float* __restrict__ qkv_w, const float* __restrict__ proj_w,
    const float* __restrict__ fc1_w, const float* __restrict__ fc2_w,
    __nv_bfloat16* __restrict__ wqkvT, __nv_bfloat16* __restrict__ wprojT,
    __nv_bfloat16* __restrict__ wfc1T, __nv_bfloat16* __restrict__ wfc2T,
    const float* __restrict__ rel_table, const int* __restrict__ rel_idx,
    const float* __restrict__ attn_mask, float* __restrict__ amask)
{
    int gid = blockIdx.x * 256 + threadIdx.x;
    if (gid < PR0) {
        wconv_elem(gid, qkv_w, wqkvT, 256, 768);
    } else if (gid < PR1) {
        wconv_elem(gid - PR0, proj_w, wprojT, 256, 256);
    } else if (gid < PR2) {
        wconv_elem(gid - PR1, fc1_w, wfc1T, 256, 1024);
    } else if (gid < PR3) {
        wconv_elem(gid - PR2, fc2_w, wfc2T, 1024, 256);
    } else if (gid < PR4) {
        int idx = gid - PR3;
        int i    = idx & 15;
        int lane = (idx >> 4) & 31;
        int seg  = (idx >> 9) & 7;
        int h    = (idx >> 12) & 7;
        int wt   = idx >> 15;
        int am = seg >> 1, half = seg & 1;
        int row = am * 16 + (lane >> 2) + half * 8;
        int col = (i >> 1) * 8 + (lane & 3) * 2 + (i & 1);
        float v = -3.402823466e38f;
        if (row < NSEQ && col < NSEQ && row != col)
            v = rel_table[rel_idx[row * NSEQ + col] * NHEADS + h]
              + attn_mask[wt * NSEQ * NSEQ + row * NSEQ + col];
        amask[idx] = v;
    }
}

// ---------------------------------------------------------------------------
// LayerNorm: warp-per-token. 8 tokens / block.
// ---------------------------------------------------------------------------
__global__ __launch_bounds__(256) void ln_kernel(
    const float* __restrict__ x,
    const float* __restrict__ gamma,
    const float* __restrict__ beta,
    __nv_bfloat16* __restrict__ out,
    int shifted)
{
    int wid = threadIdx.x >> 5, lane = threadIdx.x & 31;
    int t = blockIdx.x * 8 + wid;
    int src;
    if (shifted) {
        int wi  = t / NSEQ;
        int pos = t - wi * NSEQ;
        int b    = wi >> 6;
        int wrem = wi & 63;
        int hs = (wrem >> 3) * 7 + pos / 7;
        int ws = (wrem & 7) * 7 + pos % 7;
        int sh = hs + 3; if (sh >= 56) sh -= 56;
        int sw = ws + 3; if (sw >= 56) sw -= 56;
        src = b * 3136 + sh * 56 + sw;
    } else {
        src = t;
    }
    const float* row = x + (size_t)src * C_DIM + lane * 8;
    float4 v0 = *(const float4*)(row);
    float4 v1 = *(const float4*)(row + 4);
    float v[8] = {v0.x, v0.y, v0.z, v0.w, v1.x, v1.y, v1.z, v1.w};
    float s = 0.f, s2 = 0.f;
    #pragma unroll
    for (int i = 0; i < 8; i++) { s += v[i]; s2 += v[i] * v[i]; }
    #pragma unroll
    for (int off = 16; off; off >>= 1) {
        s  += __shfl_xor_sync(0xffffffffu, s,  off);
        s2 += __shfl_xor_sync(0xffffffffu, s2, off);
    }
    float mean = s * (1.f / 256.f);
    float var  = s2 * (1.f / 256.f) - mean * mean;
    float r = rsqrtf(var + 1e-6f);
    const float* g4 = gamma + lane * 8;
    const float* b4 = beta + lane * 8;
    uint32_t o4[4];
    #pragma unroll
    for (int i = 0; i < 4; i++) {
        float a0 = (v[2*i]   - mean) * r * g4[2*i]   + b4[2*i];
        float a1 = (v[2*i+1] - mean) * r * g4[2*i+1] + b4[2*i+1];
        o4[i] = pack2(a0, a1);
    }
    *(uint4*)(out + (size_t)t * C_DIM + lane * 8) = *(uint4*)o4;
}

// ---------------------------------------------------------------------------
// Shared GEMM epilogue.
// ---------------------------------------------------------------------------
template<int EPI>
__device__ __forceinline__ void gemm_epilogue(
    float acc[4][8][4], const float* sbias, const float* residual,
    void* outv, int Nc, int bm, int bn, int wm, int wn, int lane)
{
    const int n0 = bn + wn * 64 + (lane & 3) * 2;
    const int m0 = bm + wm * 64 + (lane >> 2);

    #pragma unroll
    for (int am = 0; am < 4; am++) {
        int mA = m0 + am * 16;
        int dstA = mA, dstB = mA + 8;
        if (EPI == 3) {
            #pragma unroll
            for (int h = 0; h < 2; h++) {
                int m = mA + h * 8;
                int wi  = m / NSEQ;
                int pos = m - wi * NSEQ;
                int b    = wi >> 6;
                int wrem = wi & 63;
                int hs = (wrem >> 3) * 7 + pos / 7;
                int ws = (wrem & 7) * 7 + pos % 7;
                int dh = hs + 3; if (dh >= 56) dh -= 56;
                int dw = ws + 3; if (dw >= 56) dw -= 56;
                int d = b * 3136 + dh * 56 + dw;
                if (h == 0) dstA = d; else dstB = d;
            }
        }
        #pragma unroll
        for (int nn = 0; nn < 8; nn++) {
            int col = n0 + nn * 8;
            float b0 = sbias[col - bn], b1 = sbias[col - bn + 1];
            float c0 = acc[am][nn][0] + b0, c1 = acc[am][nn][1] + b1;
            float c2 = acc[am][nn][2] + b0, c3 = acc[am][nn][3] + b1;
            if (EPI == 1) {
                c0 = c0 * 0.5f * (1.f + erff(c0 * 0.70710678118654752f));
                c1 = c1 * 0.5f * (1.f + erff(c1 * 0.70710678118654752f));
                c2 = c2 * 0.5f * (1.f + erff(c2 * 0.70710678118654752f));
                c3 = c3 * 0.5f * (1.f + erff(c3 * 0.70710678118654752f));
            }
            if (EPI == 0 || EPI == 1) {
                __nv_bfloat16* out = (__nv_bfloat16*)outv;
                *(uint32_t*)(out + (size_t)mA * Nc + col)       = pack2(c0, c1);
                *(uint32_t*)(out + (size_t)(mA + 8) * Nc + col) = pack2(c2, c3);
            } else {
                float* out = (float*)outv;
                float2 r0 = *(const float2*)(residual + (size_t)dstA * Nc + col);
                float2 r1 = *(const float2*)(residual + (size_t)dstB * Nc + col);
                *(float2*)(out + (size_t)dstA * Nc + col) = make_float2(c0 + r0.x, c1 + r0.y);
                *(float2*)(out + (size_t)dstB * Nc + col) = make_float2(c2 + r1.x, c3 + r1.y);
            }
        }
    }
}

// ---------------------------------------------------------------------------
// Persistent B-panel GEMM (K=256).
// ---------------------------------------------------------------------------
#define KP 40
#define BCH (128 * KP * 2)
#define PB_SMEM (8 * BCH + 3 * BCH)

template<int EPI>
__global__ __launch_bounds__(128) void gemm_pb(
    const __nv_bfloat16* __restrict__ A,
    const __nv_bfloat16* __restrict__ Bt,
    const float* __restrict__ bias,
    const float* __restrict__ residual,
    void* __restrict__ outv,
    int Nc)
{
    extern __shared__ __align__(16) uint8_t smem[];
    __shared__ float sbias[128];

    const int tid = threadIdx.x;
    const int lane = tid & 31, wid = tid >> 5;
    const int wm = wid & 1;
    const int wn = wid >> 1;
    const int bn = blockIdx.x * 128;
    const int GY = gridDim.y;

    sbias[tid] = bias[bn + tid];

    const uint32_t sBase = smem_u32(smem);
    const uint32_t aBase = sBase + 8 * BCH;

    const int lr = tid >> 2;
    const int lc = (tid & 3) * 8;

    {
        const __nv_bfloat16* Bb = Bt + (size_t)bn * 256;
        #pragma unroll
        for (int ch = 0; ch < 8; ch++)
            #pragma unroll
            for (int j = 0; j < 4; j++) {
                int r = lr + j * 32;
                CP16(sBase + ch * BCH + (uint32_t)(r * KP + lc) * 2,
                     Bb + (size_t)r * 256 + ch * 32 + lc);
            }
        CP_COMMIT();
    }

    const int nTiles = (NMT - blockIdx.y + GY - 1) / GY;
    const int T = nTiles * 8;

    #pragma unroll
    for (int s = 0; s < 2; s++) {
        if (s < T) {
            int mt = blockIdx.y + (s >> 3) * GY;
            const __nv_bfloat16* Ab = A + (size_t)mt * 128 * 256 + (s & 7) * 32;
            #pragma unroll
            for (int j = 0; j < 4; j++) {
                int r = lr + j * 32;
                CP16(aBase + s * BCH + (uint32_t)(r * KP + lc) * 2, Ab + (size_t)r * 256 + lc);
            }
        }
        CP_COMMIT();
    }

    const uint32_t aRowB = (uint32_t)(wm * 64 + (lane & 15));
    const uint32_t aKH   = (lane & 16) ? 8u : 0u;
    const uint32_t bRowB = (uint32_t)(wn * 64 + (lane & 7) + ((lane & 16) ? 8 : 0));
    const uint32_t bKH   = (lane & 8) ? 8u : 0u;

    float acc[4][8][4];
    #pragma unroll
    for (int i = 0; i < 4; i++)
        #pragma unroll
        for (int j = 0; j < 8; j++)
            #pragma unroll
            for (int t = 0; t < 4; t++) acc[i][j][t] = 0.f;

    for (int g = 0; g < T; g++) {
        int kc = g & 7;
        CP_WAIT1();
        __syncthreads();

        if (g + 2 < T) {
            int g2 = g + 2;
            int mt2 = blockIdx.y + (g2 >> 3) * GY;
            const __nv_bfloat16* Ab = A + (size_t)mt2 * 128 * 256 + (g2 & 7) * 32;
            uint32_t st = aBase + (uint32_t)(g2 % 3) * BCH;
            #pragma unroll
            for (int j = 0; j < 4; j++) {
                int r = lr + j * 32;
                CP16(st + (uint32_t)(r * KP + lc) * 2, Ab + (size_t)r * 256 + lc);
            }
        }
        CP_COMMIT();

        const uint32_t aS = aBase + (uint32_t)(g % 3) * BCH;
        const uint32_t bS = sBase + (uint32_t)kc * BCH;
        #pragma unroll
        for (int ks = 0; ks < 2; ks++) {
            uint32_t af[4][4], bf[4][4];
            #pragma unroll
            for (int am = 0; am < 4; am++)
                ldsm4(af[am], aS + ((aRowB + am * 16) * KP + ks * 16 + aKH) * 2);
            #pragma unroll
            for (int gi = 0; gi < 4; gi++)
                ldsm4(bf[gi], bS + ((bRowB + gi * 16) * KP + ks * 16 + bKH) * 2);
            #pragma unroll
            for (int am = 0; am < 4; am++)
                #pragma unroll
                for (int nn = 0; nn < 8; nn++)
                    mma16816(acc[am][nn], af[am], &bf[nn >> 1][(nn & 1) * 2]);
        }

        if (kc == 7) {
            int bm = (blockIdx.y + (g >> 3) * GY) * 128;
            gemm_epilogue<EPI>(acc, sbias, residual, outv, Nc, bm, bn, wm, wn, lane);
            #pragma unroll
            for (int i = 0; i < 4; i++)
                #pragma unroll
                for (int j = 0; j < 8; j++)
                    #pragma unroll
                    for (int t = 0; t < 4; t++) acc[i][j][t] = 0.f;
        }
    }
}

// ---------------------------------------------------------------------------
// Streaming GEMM for fc2 (K=1024): 3-stage -> 3 CTAs/SM.
// ---------------------------------------------------------------------------
#define STAGE_B (2 * BCH)
#define B_OFF   BCH
#define ST_SMEM (3 * STAGE_B)

template<int EPI>
__global__ __launch_bounds__(128, 3) void gemm_st(
    const __nv_bfloat16* __restrict__ A,
    const __nv_bfloat16* __restrict__ Bt,
    const float* __restrict__ bias,
    const float* __restrict__ residual,
    void* __restrict__ outv,
    int K, int Nc)
{
    extern __shared__ __align__(16) uint8_t smem[];
    __shared__ float sbias[128];

    const int tid = threadIdx.x;
    const int lane = tid & 31, wid = tid >> 5;
    const int wm = wid & 1;
    const int wn = wid >> 1;
    const int bn = blockIdx.x * 128, bm = blockIdx.y * 128;

    sbias[tid] = bias[bn + tid];

    const uint32_t sBase = smem_u32(smem);

    const int ldr0 = tid >> 2;
    const int ldc  = (tid & 3) * 8;

    const uint32_t aRowB = (uint32_t)(wm * 64 + (lane & 15));
    const uint32_t aKH   = (lane & 16) ? 8u : 0u;
    const uint32_t bRowB = (uint32_t)(wn * 64 + (lane & 7) + ((lane & 16) ? 8 : 0));
    const uint32_t bKH   = (lane & 8) ? 8u : 0u;

    float acc[4][8][4];
    #pragma unroll
    for (int i = 0; i < 4; i++)
        #pragma unroll
        for (int j = 0; j < 8; j++)
            #pragma unroll
            for (int t = 0; t < 4; t++) acc[i][j][t] = 0.f;

    const int nk = K >> 5;

    #pragma unroll
    for (int s = 0; s < 2; s++) {
        uint32_t st = sBase + s * STAGE_B;
        const __nv_bfloat16* Ab = A + (size_t)bm * K + s * 32;
        const __nv_bfloat16* Bb = Bt + (size_t)bn * K + s * 32;
        #pragma unroll
        for (int j = 0; j < 4; j++) {
            int r = ldr0 + j * 32;
            CP16(st + (uint32_t)(r * KP + ldc) * 2,         Ab + (size_t)r * K + ldc);
            CP16(st + B_OFF + (uint32_t)(r * KP + ldc) * 2, Bb + (size_t)r * K + ldc);
        }
        CP_COMMIT();
    }

    for (int kc = 0; kc < nk; kc++) {
        CP_WAIT1();
        __syncthreads();

        if (kc + 2 < nk) {
            uint32_t st = sBase + (uint32_t)((kc + 2) % 3) * STAGE_B;
            const __nv_bfloat16* Ab = A + (size_t)bm * K + (kc + 2) * 32;
            const __nv_bfloat16* Bb = Bt + (size_t)bn * K + (kc + 2) * 32;
            #pragma unroll
            for (int j = 0; j < 4; j++) {
                int r = ldr0 + j * 32;
                CP16(st + (uint32_t)(r * KP + ldc) * 2,         Ab + (size_t)r * K + ldc);
                CP16(st + B_OFF + (uint32_t)(r * KP + ldc) * 2, Bb + (size_t)r * K + ldc);
            }
        }
        CP_COMMIT();

        const uint32_t aS = sBase + (uint32_t)(kc % 3) * STAGE_B;
        const uint32_t bS = aS + B_OFF;
        #pragma unroll
        for (int ks = 0; ks < 2; ks++) {
            uint32_t af[4][4], bf[4][4];
            #pragma unroll
            for (int am = 0; am < 4; am++)
                ldsm4(af[am], aS + ((aRowB + am * 16) * KP + ks * 16 + aKH) * 2);
            #pragma unroll
            for (int g = 0; g < 4; g++)
                ldsm4(bf[g], bS + ((bRowB + g * 16) * KP + ks * 16 + bKH) * 2);
            #pragma unroll
            for (int am = 0; am < 4; am++)
                #pragma unroll
                for (int nn = 0; nn < 8; nn++)
                    mma16816(acc[am][nn], af[am], &bf[nn >> 1][(nn & 1) * 2]);
        }
    }

    gemm_epilogue<EPI>(acc, sbias, residual, outv, Nc, bm, bn, wm, wn, lane);
}

// ---------------------------------------------------------------------------
// Fused attention, head-group split + per-am-tile pipeline.
// Block = (window, head-group of 4), 128 threads. smem 54.5KB -> 4 CTAs/SM.
// Q packed at 49-row head stride (pad reads land in next head's data:
// harmless, those rows are masked/unstored). K keeps zeroed 64-row pads.
// ---------------------------------------------------------------------------
#define AQ_STR 40
#define AV_STR 72
#define HG      4
#define ATTN_QS   0
#define ATTN_QSZ  ((HG * 49 + 15) * AQ_STR)          // 8440 elems
#define ATTN_KB   ATTN_QSZ
#define ATTN_VT   (ATTN_KB + HG * 64 * AQ_STR)       // +10240
#define ATTN_SMEM ((ATTN_VT + HG * 32 * AV_STR) * 2) // 55792 B

__global__ __launch_bounds__(128, 4) void attn_kernel(
    const __nv_bfloat16* __restrict__ qkv,
    const float* __restrict__ amask,
    const float* __restrict__ temperature,
    __nv_bfloat16* __restrict__ o)
{
    extern __shared__ __align__(16) __nv_bfloat16 sm[];
    const int wi = blockIdx.x;
    const int hg = blockIdx.y;
    const int tid = threadIdx.x;
    const int hl = tid >> 5, lane = tid & 31;
    const int h = hg * HG + hl;

    const float scale = expf(temperature[0]);
    const __nv_bfloat16* base = qkv + (size_t)wi * NSEQ * 768;

    {
        uint4 z = make_uint4(0, 0, 0, 0);
        uint4* v = (uint4*)(sm + ATTN_VT);
        for (int i = tid; i < HG * 32 * AV_STR / 8; i += 128) v[i] = z;
        for (int i = tid; i < HG * 15 * 5; i += 128) {
            int hh = i / 75, rem = i - hh * 75;
            int row = 49 + rem / 5, q = rem % 5;
            *((uint4*)(sm + ATTN_KB + (hh * 64 + row) * AQ_STR) + q) = z;
        }
    }
    for (int idx = tid; idx < NSEQ * 48; idx += 128) {
        int r = idx / 48, u = idx - r * 48;
        int ten = u >> 4;
        int seg = u & 15;
        int hh  = seg >> 2;
        int cw  = (seg & 3) * 8;
        uint4 val = *(const uint4*)(base + (size_t)r * 768 + ten * 256 + hg * 128 + hh * 32 + cw);
        if (ten == 0) {
            *(uint4*)(sm + ATTN_QS + (hh * 49 + r) * AQ_STR + cw) = val;
        } else if (ten == 1) {
            *(uint4*)(sm + ATTN_KB + (hh * 64 + r) * AQ_STR + cw) = val;
        } else {
            const __nv_bfloat16* e = (const __nv_bfloat16*)&val;
            __nv_bfloat16* vt = sm + ATTN_VT + hh * 32 * AV_STR;
            #pragma unroll
            for (int j = 0; j < 8; j++) vt[(cw + j) * AV_STR + r] = e[j];
        }
    }
    __syncthreads();

    const uint32_t qB = smem_u32(sm + ATTN_QS + hl * 49 * AQ_STR);
    const uint32_t kB = smem_u32(sm + ATTN_KB + hl * 64 * AQ_STR);
    const uint32_t vB = smem_u32(sm + ATTN_VT + hl * 32 * AV_STR);

    const uint32_t aRow = (uint32_t)(lane & 15);
    const uint32_t aKH  = (lane & 16) ? 8u : 0u;
    const uint32_t bRow = (uint32_t)((lane & 7) + ((lane & 16) ? 8 : 0));
    const uint32_t bKH  = (lane & 8) ? 8u : 0u;

    // K fragments held across the am loop (32 regs)
    uint32_t kbf[2][4][4];
    #pragma unroll
    for (int ks = 0; ks < 2; ks++)
        #pragma unroll
        for (int g = 0; g < 4; g++)
            ldsm4(kbf[ks][g], kB + ((bRow + g * 16) * AQ_STR + ks * 16 + bKH) * 2);

    const float* tb = amask + (((size_t)(wi & 63) * 8 + h) << 12);

    #pragma unroll
    for (int am = 0; am < 4; am++) {
        // --- QK for this 16-row tile ---
        float acc[8][4];
        #pragma unroll
        for (int j = 0; j < 8; j++)
            #pragma unroll
            for (int t = 0; t < 4; t++) acc[j][t] = 0.f;
        #pragma unroll
        for (int ks = 0; ks < 2; ks++) {
            uint32_t af[4];
            ldsm4(af, qB + ((aRow + am * 16) * AQ_STR + ks * 16 + aKH) * 2);
            #pragma unroll
            for (int nn = 0; nn < 8; nn++)
                mma16816(acc[nn], af, &kbf[ks][nn >> 1][(nn & 1) * 2]);
        }

        // --- softmax -> P fragments for this tile ---
        uint32_t afP[4][4];
        #pragma unroll
        for (int half = 0; half < 2; half++) {
            const float4* tseg = (const float4*)(tb + (((am << 1) + half) << 9) + (lane << 4));
            float4 t0 = tseg[0], t1 = tseg[1], t2 = tseg[2], t3 = tseg[3];
            float tv[16] = {t0.x, t0.y, t0.z, t0.w, t1.x, t1.y, t1.z, t1.w,
                            t2.x, t2.y, t2.z, t2.w, t3.x, t3.y, t3.z, t3.w};
            float e[16];
            float mx = -3.402823466e38f;
            #pragma unroll
            for (int nt = 0; nt < 8; nt++) {
                #pragma unroll
                for (int j = 0; j < 2; j++) {
                    float s = fmaf(acc[nt][half * 2 + j], scale, tv[nt * 2 + j]);
                    e[nt * 2 + j] = s;
                    mx = fmaxf(mx, s);
                }
            }
            mx = fmaxf(mx, __shfl_xor_sync(0xffffffffu, mx, 1));
            mx = fmaxf(mx, __shfl_xor_sync(0xffffffffu, mx, 2));
            float sum = 0.f;
            #pragma unroll
            for (int i = 0; i < 16; i++) { e[i] = fexp(e[i] - mx); sum += e[i]; }
            sum += __shfl_xor_sync(0xffffffffu, sum, 1);
            sum += __shfl_xor_sync(0xffffffffu, sum, 2);
            float inv = 1.f / sum;
            #pragma unroll
            for (int ks = 0; ks < 4; ks++) {
                afP[ks][half]     = pack2(e[4 * ks] * inv,     e[4 * ks + 1] * inv);
                afP[ks][2 + half] = pack2(e[4 * ks + 2] * inv, e[4 * ks + 3] * inv);
            }
        }

        // --- P*V for this tile ---
        float accP[4][4];
        #pragma unroll
        for (int j = 0; j < 4; j++)
            #pragma unroll
            for (int t = 0; t < 4; t++) accP[j][t] = 0.f;
        #pragma unroll
        for (int ks = 0; ks < 4; ks++) {
            uint32_t vbf[2][4];
            #pragma unroll
            for (int g = 0; g < 2; g++)
                ldsm4(vbf[g], vB + ((bRow + g * 16) * AV_STR + ks * 16 + bKH) * 2);
            #pragma unroll
            for (int nn = 0; nn < 4; nn++)
                mma16816(accP[nn], afP[ks], &vbf[nn >> 1][(nn & 1) * 2]);
        }

        // --- store this tile ---
        int n = am * 16 + (lane >> 2);
        int d0 = (lane & 3) * 2;
        #pragma unroll
        for (int nn = 0; nn < 4; nn++) {
            int d = d0 + nn * 8;
            if (n < NSEQ)
                *(uint32_t*)(o + (size_t)(wi * NSEQ + n) * C_DIM + h * HDIM + d)
                    = pack2(accP[nn][0], accP[nn][1]);
            if (n + 8 < NSEQ)
                *(uint32_t*)(o + (size_t)(wi * NSEQ + n + 8) * C_DIM + h * HDIM + d)
                    = pack2(accP[nn][2], accP[nn][3]);
        }
    }
}

// ---------------------------------------------------------------------------
extern "C" void kernel_launch(void* const* d_in, const int* in_sizes, int n_in,
                              void* d_out, int out_size)
{
    const float* x        = (const float*)d_in[0];
    const float* attn_msk = (const float*)d_in[1];
    const float* norm1_g  = (const float*)d_in[2];
    const float* norm1_b  = (const float*)d_in[3];
    const float* qkv_w    = (const float*)d_in[4];
    const float* qkv_b    = (const float*)d_in[5];
    const float* temp     = (const float*)d_in[6];
    const float* rel_tab  = (const float*)d_in[7];
    const float* proj_w   = (const float*)d_in[8];
    const float* proj_b   = (const float*)d_in[9];
    const float* norm2_g  = (const float*)d_in[10];
    const float* norm2_b  = (const float*)d_in[11];
    const float* fc1_w    = (const float*)d_in[12];
    const float* fc1_b    = (const float*)d_in[13];
    const float* fc2_w    = (const float*)d_in[14];
    const float* fc2_b    = (const float*)d_in[15];
    const int*   rel_idx  = (const int*)d_in[16];
    float* out = (float*)d_out;

    __nv_bfloat16 *zw, *qkv, *o, *hbuf, *fc1, *wqkvT, *wprojT, *wfc1T, *wfc2T;
    float *x2, *amask;
    cudaGetSymbolAddress((void**)&zw,    g_zw);
    cudaGetSymbolAddress((void**)&qkv,   g_qkv);
    cudaGetSymbolAddress((void**)&o,     g_o);
    cudaGetSymbolAddress((void**)&x2,    g_x2);
    cudaGetSymbolAddress((void**)&hbuf,  g_h);
    cudaGetSymbolAddress((void**)&fc1,   g_fc1);
    cudaGetSymbolAddress((void**)&wqkvT, g_wqkvT);
    cudaGetSymbolAddress((void**)&wprojT,g_wprojT);
    cudaGetSymbolAddress((void**)&wfc1T, g_wfc1T);
    cudaGetSymbolAddress((void**)&wfc2T, g_wfc2T);
    cudaGetSymbolAddress((void**)&amask, g_amask);

    static bool attr_done = false;
    if (!attr_done) {
        cudaFuncSetAttribute(gemm_pb<0>, cudaFuncAttributeMaxDynamicSharedMemorySize, PB_SMEM);
        cudaFuncSetAttribute(gemm_pb<1>, cudaFuncAttributeMaxDynamicSharedMemorySize, PB_SMEM);
        cudaFuncSetAttribute(gemm_pb<3>, cudaFuncAttributeMaxDynamicSharedMemorySize, PB_SMEM);
        cudaFuncSetAttribute(gemm_st<2>, cudaFuncAttributeMaxDynamicSharedMemorySize, ST_SMEM);
        cudaFuncSetAttribute(attn_kernel, cudaFuncAttributeMaxDynamicSharedMemorySize, ATTN_SMEM);
        attr_done = true;
    }

    prep_kernel<<<(PR4 + 255) / 256, 256>>>(qkv_w, proj_w, fc1_w, fc2_w,
                                            wqkvT, wprojT, wfc1T, wfc2T,
                                            rel_tab, rel_idx, attn_msk, amask);   // 0
    ln_kernel<<<M_TOK / 8, 256>>>(x, norm1_g, norm1_b, zw, 1);                     // 1
    gemm_pb<0><<<dim3(6, 48), 128, PB_SMEM>>>(zw, wqkvT, qkv_b, nullptr, qkv, 768);// 2
    attn_kernel<<<dim3(NWIN, 2), 128, ATTN_SMEM>>>(qkv, amask, temp, o);           // 3
    gemm_pb<3><<<dim3(2, 148), 128, PB_SMEM>>>(o, wprojT, proj_b, x, x2, 256);     // 4
    ln_kernel<<<M_TOK / 8, 256>>>(x2, norm2_g, norm2_b, hbuf, 0);                  // 5
    gemm_pb<1><<<dim3(8, 37), 128, PB_SMEM>>>(hbuf, wfc1T, fc1_b, nullptr, fc1, 1024); // 6
    gemm_st<2><<<dim3(2, NMT), 128, ST_SMEM>>>(fc1, wfc2T, fc2_b, x2, out, 1024, 256); // 7
}